// round 1
// baseline (speedup 1.0000x reference)
#include <cuda_runtime.h>
#include <cstdint>

// Problem constants (from reference): B=8192, D=128
#define BDIM 8192
#define DDIM 128
#define BM 256              // rows per block (one per thread)
#define BN 256              // columns per segment (grid.y)
#define CH 32               // columns staged per smem chunk
#define NSEG (BDIM / BN)    // 32
#define TEMP_INV 10.0f      // 1 / 0.1
#define TTHRESH 365

// Scratch (device globals: no allocation allowed in kernel_launch)
__device__ float  g_z[BDIM * DDIM];            // normalized embeddings, 4 MB
__device__ float2 g_part[BDIM * NSEG];         // per (row, seg): (sum_all, sum_pos), 2 MB
__device__ float  g_bsum[BDIM / 256];          // per-combine-block partial sums
__device__ float  g_bcnt[BDIM / 256];

// ---- packed f32x2 helpers (sm_100+ PTX) ----
__device__ __forceinline__ unsigned long long fma2(unsigned long long a,
                                                   unsigned long long b,
                                                   unsigned long long c) {
    unsigned long long d;
    asm("fma.rn.f32x2 %0, %1, %2, %3;" : "=l"(d) : "l"(a), "l"(b), "l"(c));
    return d;
}
__device__ __forceinline__ unsigned long long add2(unsigned long long a,
                                                   unsigned long long b) {
    unsigned long long d;
    asm("add.rn.f32x2 %0, %1, %2;" : "=l"(d) : "l"(a), "l"(b));
    return d;
}
__device__ __forceinline__ float lo32(unsigned long long v) {
    return __int_as_float((int)(unsigned)(v & 0xFFFFFFFFull));
}
__device__ __forceinline__ float hi32(unsigned long long v) {
    return __int_as_float((int)(unsigned)(v >> 32));
}

// ---- Kernel 1: L2-normalize rows. One warp per row. ----
__global__ void norm_kernel(const float* __restrict__ emb) {
    int row  = blockIdx.x * 8 + threadIdx.y;   // blockDim = (32, 8)
    int lane = threadIdx.x;
    const float4* src = (const float4*)(emb + (size_t)row * DDIM);
    float4 v = src[lane];                       // 32 lanes * 4 = 128
    float ss = v.x * v.x + v.y * v.y + v.z * v.z + v.w * v.w;
    #pragma unroll
    for (int o = 16; o; o >>= 1) ss += __shfl_xor_sync(0xFFFFFFFFu, ss, o);
    float inv = rsqrtf(fmaxf(ss, 1e-24f));
    inv = inv * (1.5f - 0.5f * ss * inv * inv);  // one NR step for accuracy
    float4 o4 = make_float4(v.x * inv, v.y * inv, v.z * inv, v.w * inv);
    ((float4*)(g_z + (size_t)row * DDIM))[lane] = o4;
}

// ---- Kernel 2: fused similarity + masked exp-sums ----
// grid = (B/BM, B/BN); each thread owns row i, processes columns [j0, j0+BN).
__global__ void __launch_bounds__(BM, 1)
main_kernel(const int* __restrict__ st, const int* __restrict__ cen) {
    __shared__ float4 s_col[CH][DDIM / 4];  // 32 cols x 128 floats = 16 KB
    __shared__ int    s_t[CH];

    const int tid = threadIdx.x;
    const int i   = blockIdx.x * BM + tid;
    const int ti  = st[i];
    const bool cenf = (cen[i] == 1);

    // Load row z_i into registers as 64 packed f32x2 (128 regs)
    unsigned long long zi[DDIM / 2];
    const ulonglong2* zr = (const ulonglong2*)(g_z + (size_t)i * DDIM);
    #pragma unroll
    for (int k = 0; k < DDIM / 4; k++) {
        ulonglong2 v = zr[k];
        zi[2 * k]     = v.x;
        zi[2 * k + 1] = v.y;
    }

    float s_all = 0.0f, s_pos = 0.0f;
    const int j0 = blockIdx.y * BN;

    for (int c = 0; c < BN / CH; c++) {
        const int jc = j0 + c * CH;
        __syncthreads();
        // Cooperative stage of CH columns (32 rows x 128 floats) into smem
        #pragma unroll
        for (int u = 0; u < (CH * DDIM / 4) / BM; u++) {   // 4 iters
            int idx = u * BM + tid;
            int r = idx >> 5, k = idx & 31;                // 32 float4 per row
            s_col[r][k] = ((const float4*)(g_z + (size_t)(jc + r) * DDIM))[k];
        }
        if (tid < CH) s_t[tid] = st[jc + tid];
        __syncthreads();

        #pragma unroll 2
        for (int jj = 0; jj < CH; jj++) {
            const ulonglong2* col = (const ulonglong2*)&s_col[jj][0]; // 32 x 16B, broadcast
            unsigned long long a0 = 0ull, a1 = 0ull, a2 = 0ull, a3 = 0ull;
            #pragma unroll
            for (int k = 0; k < 32; k += 2) {
                ulonglong2 v0 = col[k];
                ulonglong2 v1 = col[k + 1];
                a0 = fma2(zi[2 * k],     v0.x, a0);
                a1 = fma2(zi[2 * k + 1], v0.y, a1);
                a2 = fma2(zi[2 * k + 2], v1.x, a2);
                a3 = fma2(zi[2 * k + 3], v1.y, a3);
            }
            a0 = add2(a0, a1);
            a2 = add2(a2, a3);
            a0 = add2(a0, a2);
            float dot = lo32(a0) + hi32(a0);
            float e   = __expf(dot * TEMP_INV);   // sim in [-10,10]: no overflow
            int  j    = jc + jj;
            bool self = (j == i);
            if (!self) s_all += e;
            int td = ti - s_t[jj];
            td = td < 0 ? -td : td;
            bool p = cenf && !self && (td < TTHRESH);
            if (p) s_pos += e;
        }
    }
    g_part[(size_t)i * NSEG + blockIdx.y] = make_float2(s_all, s_pos);
}

// ---- Kernel 3: per-row merge + deterministic block partial reduction ----
__global__ void combine_kernel() {
    __shared__ float sh_s[256];
    __shared__ float sh_c[256];
    int tid = threadIdx.x;
    int row = blockIdx.x * 256 + tid;
    float sa = 0.0f, sp = 0.0f;
    #pragma unroll
    for (int s = 0; s < NSEG; s++) {
        float2 v = g_part[(size_t)row * NSEG + s];
        sa += v.x;
        sp += v.y;
    }
    float pr = 0.0f, c = 0.0f;
    if (sp > 0.0f) {
        pr = logf(sa) - logf(sp);
        c  = 1.0f;
    }
    sh_s[tid] = pr;
    sh_c[tid] = c;
    __syncthreads();
    #pragma unroll
    for (int o = 128; o > 0; o >>= 1) {
        if (tid < o) {
            sh_s[tid] += sh_s[tid + o];
            sh_c[tid] += sh_c[tid + o];
        }
        __syncthreads();
    }
    if (tid == 0) {
        g_bsum[blockIdx.x] = sh_s[0];
        g_bcnt[blockIdx.x] = sh_c[0];
    }
}

// ---- Kernel 4: final scalar ----
__global__ void final_kernel(float* __restrict__ out) {
    int lane = threadIdx.x;  // 32 threads, 32 partials
    float s = g_bsum[lane];
    float c = g_bcnt[lane];
    #pragma unroll
    for (int o = 16; o; o >>= 1) {
        s += __shfl_xor_sync(0xFFFFFFFFu, s, o);
        c += __shfl_xor_sync(0xFFFFFFFFu, c, o);
    }
    if (lane == 0) out[0] = (c > 0.0f) ? (s / c) : 0.0f;
}

extern "C" void kernel_launch(void* const* d_in, const int* in_sizes, int n_in,
                              void* d_out, int out_size) {
    const float* emb = (const float*)d_in[0];
    const int*   st  = (const int*)d_in[1];
    const int*   cenp = (const int*)d_in[2];
    float* out = (float*)d_out;

    norm_kernel<<<BDIM / 8, dim3(32, 8)>>>(emb);
    dim3 grid(BDIM / BM, BDIM / BN);
    main_kernel<<<grid, BM>>>(st, cenp);
    combine_kernel<<<BDIM / 256, 256>>>();
    final_kernel<<<1, 32>>>(out);
}

// round 3
// speedup vs baseline: 3.4858x; 3.4858x over previous
#include <cuda_runtime.h>
#include <cuda_bf16.h>
#include <cstdint>

// B=8192, D=128. sim = (Z Z^T)/0.1 with masked logsumexps -> scalar mean.
// Strategy: bf16 hi/lo split folded into one K=384 GEMM on mma.sync (HMMA):
//   A = [10*z_hi | 10*z_hi | 10*z_lo],  Bt = [z_hi | z_lo | z_hi]
//   A . Bt^T = 10*(zh.zh + zh.zl + zl.zh) ~= 10*sim  (lo*lo dropped, ~1e-6)
#define BDIM 8192
#define DDIM 128
#define KTOT 384
#define TM   128
#define TN   128
#define KC   64             // K chunk per stage (64 bf16 = 128B rows)
#define NSEG 128            // 64 col-tiles * 2 warpN halves
#define TTHRESH 365

__device__ __nv_bfloat16 g_za[BDIM * KTOT];   // 6MB
__device__ __nv_bfloat16 g_zb[BDIM * KTOT];   // 6MB
__device__ float2 g_part[BDIM * NSEG];        // 8MB
__device__ float  g_bsum[BDIM / 256];
__device__ float  g_bcnt[BDIM / 256];

// ---------------- PTX helpers (all sm_80-portable: no 'a'-gated features) ---
__device__ __forceinline__ uint32_t smem_u32(const void* p) {
    uint32_t a;
    asm("{ .reg .u64 t; cvta.to.shared.u64 t, %1; cvt.u32.u64 %0, t; }" : "=r"(a) : "l"(p));
    return a;
}
__device__ __forceinline__ void cp16(uint32_t dst, const void* src) {
    asm volatile("cp.async.cg.shared.global [%0], [%1], 16;" :: "r"(dst), "l"(src));
}
__device__ __forceinline__ void cp_commit() {
    asm volatile("cp.async.commit_group;" ::: "memory");
}
template <int N> __device__ __forceinline__ void cp_wait() {
    asm volatile("cp.async.wait_group %0;" :: "n"(N) : "memory");
}
__device__ __forceinline__ void ldsm4(uint32_t& r0, uint32_t& r1, uint32_t& r2,
                                      uint32_t& r3, uint32_t addr) {
    asm volatile("ldmatrix.sync.aligned.m8n8.x4.shared.b16 {%0,%1,%2,%3}, [%4];"
                 : "=r"(r0), "=r"(r1), "=r"(r2), "=r"(r3) : "r"(addr));
}
__device__ __forceinline__ void mma16816(float& d0, float& d1, float& d2, float& d3,
                                         uint32_t a0, uint32_t a1, uint32_t a2,
                                         uint32_t a3, uint32_t b0, uint32_t b1) {
    asm volatile(
        "mma.sync.aligned.m16n8k16.row.col.f32.bf16.bf16.f32 "
        "{%0,%1,%2,%3}, {%4,%5,%6,%7}, {%8,%9}, {%0,%1,%2,%3};"
        : "+f"(d0), "+f"(d1), "+f"(d2), "+f"(d3)
        : "r"(a0), "r"(a1), "r"(a2), "r"(a3), "r"(b0), "r"(b1));
}

// SMEM layout (dynamic): [bufA0 16K][bufB0 16K][bufA1 16K][bufB1 16K][ti 512][cen 512][tj 512]
#define SM_STAGE 32768
#define SM_TI  65536
#define SM_CEN 66048
#define SM_TJ  66560
#define SMEM_TOTAL 67584

// ---- Kernel 1: normalize rows, bf16 hi/lo split into K=384 layouts ----
__global__ void norm_kernel(const float* __restrict__ emb) {
    int row  = blockIdx.x * 8 + threadIdx.y;   // blockDim (32,8)
    int lane = threadIdx.x;
    float4 v = ((const float4*)(emb + (size_t)row * DDIM))[lane];
    float ss = v.x * v.x + v.y * v.y + v.z * v.z + v.w * v.w;
    #pragma unroll
    for (int o = 16; o; o >>= 1) ss += __shfl_xor_sync(0xFFFFFFFFu, ss, o);
    float inv = rsqrtf(fmaxf(ss, 1e-24f));
    inv = inv * (1.5f - 0.5f * ss * inv * inv);
    float z[4] = {v.x * inv, v.y * inv, v.z * inv, v.w * inv};
    __nv_bfloat16 h[4], l[4], h10[4], l10[4];
    #pragma unroll
    for (int k = 0; k < 4; k++) {
        h[k] = __float2bfloat16_rn(z[k]);
        l[k] = __float2bfloat16_rn(z[k] - __bfloat162float(h[k]));
        float z10 = z[k] * 10.0f;
        h10[k] = __float2bfloat16_rn(z10);
        l10[k] = __float2bfloat16_rn(z10 - __bfloat162float(h10[k]));
    }
    size_t base = (size_t)row * KTOT + lane * 4;
    // A-side (scaled by 10): [h10 | h10 | l10]
    *(uint2*)(g_za + base)       = *(uint2*)h10;
    *(uint2*)(g_za + base + 128) = *(uint2*)h10;
    *(uint2*)(g_za + base + 256) = *(uint2*)l10;
    // B-side: [h | l | h]
    *(uint2*)(g_zb + base)       = *(uint2*)h;
    *(uint2*)(g_zb + base + 128) = *(uint2*)l;
    *(uint2*)(g_zb + base + 256) = *(uint2*)h;
}

// ---- Kernel 2: mma.sync GEMM (128x128 tile, K=384) + fused epilogue ----
// grid = (64, 64), 256 threads = 8 warps in 4(M) x 2(N); warp tile 32x64.
__global__ void __launch_bounds__(256, 1)
main_kernel(const int* __restrict__ st, const int* __restrict__ cen) {
    extern __shared__ char smem[];
    const uint32_t sb = smem_u32(smem);
    const int tid   = threadIdx.x;
    const int wid   = tid >> 5;
    const int lane  = tid & 31;
    const int warpM = wid >> 1;
    const int warpN = wid & 1;
    const int rBase = blockIdx.x * TM;
    const int cBase = blockIdx.y * TN;

    int*  sTi  = (int*)(smem + SM_TI);
    int*  sCen = (int*)(smem + SM_CEN);
    int*  sTj  = (int*)(smem + SM_TJ);
    if (tid < 128) {
        sTi[tid]  = st[rBase + tid];
        sCen[tid] = cen[rBase + tid];
    } else {
        sTj[tid - 128] = st[cBase + tid - 128];
    }

    // cp.async staging of one K-chunk (64 bf16 = 8 x 16B per row) for A and B
    auto load_chunk = [&](int c, int buf) {
        uint32_t bA = sb + buf * SM_STAGE;
        uint32_t bB = bA + 16384;
        #pragma unroll
        for (int u = 0; u < 4; u++) {
            int idx = u * 256 + tid;
            int row = idx >> 3, cc = idx & 7;
            uint32_t sw = (uint32_t)row * 128 + (uint32_t)((cc ^ (row & 7)) << 4);
            cp16(bA + sw, g_za + (size_t)(rBase + row) * KTOT + c * KC + cc * 8);
            cp16(bB + sw, g_zb + (size_t)(cBase + row) * KTOT + c * KC + cc * 8);
        }
        cp_commit();
    };

    load_chunk(0, 0);
    load_chunk(1, 1);

    float acc[2][8][4];
    #pragma unroll
    for (int mf = 0; mf < 2; mf++)
        #pragma unroll
        for (int nf = 0; nf < 8; nf++)
            #pragma unroll
            for (int r = 0; r < 4; r++) acc[mf][nf][r] = 0.0f;

    // ldmatrix per-thread row/col pieces
    const int trow = lane & 7;
    const int tg1  = (lane >> 3) & 1;   // +8 row offset
    const int cadd = lane >> 4;         // +1 16B-chunk offset
    const int rowA0 = warpM * 32 + tg1 * 8 + trow;       // + mf*16
    const int rowB0 = warpN * 64 + tg1 * 8 + trow;       // + np*16

    #pragma unroll
    for (int c = 0; c < 6; c++) {
        if (c < 5) cp_wait<1>(); else cp_wait<0>();
        __syncthreads();
        uint32_t bA = sb + (c & 1) * SM_STAGE;
        uint32_t bB = bA + 16384;

        #pragma unroll
        for (int kk = 0; kk < 4; kk++) {
            uint32_t aF[2][4], bF[4][4];
            #pragma unroll
            for (int mf = 0; mf < 2; mf++) {
                int row = rowA0 + mf * 16;
                uint32_t a = bA + row * 128
                           + (((kk * 2 + cadd) ^ (row & 7)) << 4);
                ldsm4(aF[mf][0], aF[mf][1], aF[mf][2], aF[mf][3], a);
            }
            #pragma unroll
            for (int np = 0; np < 4; np++) {
                int row = rowB0 + np * 16;
                uint32_t a = bB + row * 128
                           + (((kk * 2 + cadd) ^ (row & 7)) << 4);
                ldsm4(bF[np][0], bF[np][1], bF[np][2], bF[np][3], a);
            }
            #pragma unroll
            for (int mf = 0; mf < 2; mf++)
                #pragma unroll
                for (int np = 0; np < 4; np++) {
                    mma16816(acc[mf][np * 2][0], acc[mf][np * 2][1],
                             acc[mf][np * 2][2], acc[mf][np * 2][3],
                             aF[mf][0], aF[mf][1], aF[mf][2], aF[mf][3],
                             bF[np][0], bF[np][2]);
                    mma16816(acc[mf][np * 2 + 1][0], acc[mf][np * 2 + 1][1],
                             acc[mf][np * 2 + 1][2], acc[mf][np * 2 + 1][3],
                             aF[mf][0], aF[mf][1], aF[mf][2], aF[mf][3],
                             bF[np][1], bF[np][3]);
                }
        }
        __syncthreads();
        if (c + 2 < 6) load_chunk(c + 2, c & 1);
    }

    // ---- epilogue: acc = 10*sim. exp + masks + quad reduce + partial write --
    const int q  = lane >> 2;
    const int c2 = (lane & 3) * 2;
    const int seg = blockIdx.y * 2 + warpN;

    #pragma unroll
    for (int mf = 0; mf < 2; mf++) {
        int lr0 = warpM * 32 + mf * 16 + q;     // local rows lr0, lr0+8
        int lr1 = lr0 + 8;
        int i0 = rBase + lr0, i1 = rBase + lr1;
        int ti0 = sTi[lr0], ti1 = sTi[lr1];
        bool cen0 = (sCen[lr0] == 1), cen1 = (sCen[lr1] == 1);
        float sa0 = 0.f, sp0 = 0.f, sa1 = 0.f, sp1 = 0.f;
        #pragma unroll
        for (int nf = 0; nf < 8; nf++) {
            #pragma unroll
            for (int cc = 0; cc < 2; cc++) {
                int lc = warpN * 64 + nf * 8 + c2 + cc;
                int j  = cBase + lc;
                int tj = sTj[lc];
                float e0 = __expf(acc[mf][nf][cc]);
                float e1 = __expf(acc[mf][nf][2 + cc]);
                if (j != i0) {
                    sa0 += e0;
                    int td = ti0 - tj; td = td < 0 ? -td : td;
                    if (cen0 && td < TTHRESH) sp0 += e0;
                }
                if (j != i1) {
                    sa1 += e1;
                    int td = ti1 - tj; td = td < 0 ? -td : td;
                    if (cen1 && td < TTHRESH) sp1 += e1;
                }
            }
        }
        #pragma unroll
        for (int o = 1; o <= 2; o <<= 1) {
            sa0 += __shfl_xor_sync(0xFFFFFFFFu, sa0, o);
            sp0 += __shfl_xor_sync(0xFFFFFFFFu, sp0, o);
            sa1 += __shfl_xor_sync(0xFFFFFFFFu, sa1, o);
            sp1 += __shfl_xor_sync(0xFFFFFFFFu, sp1, o);
        }
        if ((lane & 3) == 0) {
            g_part[(size_t)i0 * NSEG + seg] = make_float2(sa0, sp0);
            g_part[(size_t)i1 * NSEG + seg] = make_float2(sa1, sp1);
        }
    }
}

// ---- Kernel 3: per-row merge + block partial reduction ----
__global__ void combine_kernel() {
    __shared__ float sh_s[256], sh_c[256];
    int tid = threadIdx.x;
    int row = blockIdx.x * 256 + tid;
    float sa = 0.0f, sp = 0.0f;
    const float4* p = (const float4*)(g_part + (size_t)row * NSEG);
    #pragma unroll
    for (int s = 0; s < NSEG / 2; s++) {
        float4 v = p[s];
        sa += v.x + v.z;
        sp += v.y + v.w;
    }
    float pr = 0.0f, c = 0.0f;
    if (sp > 0.0f) { pr = logf(sa) - logf(sp); c = 1.0f; }
    sh_s[tid] = pr; sh_c[tid] = c;
    __syncthreads();
    #pragma unroll
    for (int o = 128; o > 0; o >>= 1) {
        if (tid < o) { sh_s[tid] += sh_s[tid + o]; sh_c[tid] += sh_c[tid + o]; }
        __syncthreads();
    }
    if (tid == 0) { g_bsum[blockIdx.x] = sh_s[0]; g_bcnt[blockIdx.x] = sh_c[0]; }
}

__global__ void final_kernel(float* __restrict__ out) {
    int lane = threadIdx.x;
    float s = g_bsum[lane], c = g_bcnt[lane];
    #pragma unroll
    for (int o = 16; o; o >>= 1) {
        s += __shfl_xor_sync(0xFFFFFFFFu, s, o);
        c += __shfl_xor_sync(0xFFFFFFFFu, c, o);
    }
    if (lane == 0) out[0] = (c > 0.0f) ? (s / c) : 0.0f;
}

extern "C" void kernel_launch(void* const* d_in, const int* in_sizes, int n_in,
                              void* d_out, int out_size) {
    const float* emb = (const float*)d_in[0];
    const int*   st  = (const int*)d_in[1];
    const int*   cn  = (const int*)d_in[2];
    float* out = (float*)d_out;

    cudaFuncSetAttribute(main_kernel, cudaFuncAttributeMaxDynamicSharedMemorySize,
                         SMEM_TOTAL);

    norm_kernel<<<BDIM / 8, dim3(32, 8)>>>(emb);
    main_kernel<<<dim3(BDIM / TM, BDIM / TN), 256, SMEM_TOTAL>>>(st, cn);
    combine_kernel<<<BDIM / 256, 256>>>();
    final_kernel<<<1, 32>>>(out);
}

// round 4
// speedup vs baseline: 3.6532x; 1.0480x over previous
#include <cuda_runtime.h>
#include <cuda_bf16.h>
#include <cstdint>

// B=8192, D=128. sim = (Z Z^T)/0.1 with masked logsumexps -> scalar mean.
// bf16 hi/lo split folded into one K=384 GEMM on mma.sync:
//   A = [10*z_hi | 10*z_hi | 10*z_lo],  Bt = [z_hi | z_lo | z_hi]
// Symmetry: only upper-triangle tiles (2080 of 4096); off-diag tiles emit
// both row-anchored and col-anchored partial sums.
#define BDIM 8192
#define DDIM 128
#define KTOT 384
#define TM   128
#define TN   128
#define KC   64
#define NSEG 128
#define NT   64             // 8192/128 tile blocks per dim
#define TTHRESH 365

__device__ __nv_bfloat16 g_za[BDIM * KTOT];   // 6MB
__device__ __nv_bfloat16 g_zb[BDIM * KTOT];   // 6MB
__device__ float2 g_part[BDIM * NSEG];        // 8MB
__device__ float  g_bsum[BDIM / 256];
__device__ float  g_bcnt[BDIM / 256];

// ---------------- PTX helpers (sm_80-portable only) ----------------
__device__ __forceinline__ uint32_t smem_u32(const void* p) {
    uint32_t a;
    asm("{ .reg .u64 t; cvta.to.shared.u64 t, %1; cvt.u32.u64 %0, t; }" : "=r"(a) : "l"(p));
    return a;
}
__device__ __forceinline__ void cp16(uint32_t dst, const void* src) {
    asm volatile("cp.async.cg.shared.global [%0], [%1], 16;" :: "r"(dst), "l"(src));
}
__device__ __forceinline__ void cp_commit() {
    asm volatile("cp.async.commit_group;" ::: "memory");
}
template <int N> __device__ __forceinline__ void cp_wait() {
    asm volatile("cp.async.wait_group %0;" :: "n"(N) : "memory");
}
__device__ __forceinline__ void ldsm4(uint32_t& r0, uint32_t& r1, uint32_t& r2,
                                      uint32_t& r3, uint32_t addr) {
    asm volatile("ldmatrix.sync.aligned.m8n8.x4.shared.b16 {%0,%1,%2,%3}, [%4];"
                 : "=r"(r0), "=r"(r1), "=r"(r2), "=r"(r3) : "r"(addr));
}
__device__ __forceinline__ void mma16816(float& d0, float& d1, float& d2, float& d3,
                                         uint32_t a0, uint32_t a1, uint32_t a2,
                                         uint32_t a3, uint32_t b0, uint32_t b1) {
    asm volatile(
        "mma.sync.aligned.m16n8k16.row.col.f32.bf16.bf16.f32 "
        "{%0,%1,%2,%3}, {%4,%5,%6,%7}, {%8,%9}, {%0,%1,%2,%3};"
        : "+f"(d0), "+f"(d1), "+f"(d2), "+f"(d3)
        : "r"(a0), "r"(a1), "r"(a2), "r"(a3), "r"(b0), "r"(b1));
}

// SMEM: 3 stages x (A 16K + B 16K) | colp 4K | ti/cenR/tj/cenC 4x512
#define SM_STAGE 32768
#define SM_COLP  98304
#define SM_TI    102400
#define SM_CENR  102912
#define SM_TJ    103424
#define SM_CENC  103936
#define SMEM_TOTAL 104448

// ---- Kernel 1: normalize + bf16 hi/lo split, K=384 layouts ----
__global__ void norm_kernel(const float* __restrict__ emb) {
    int row  = blockIdx.x * 8 + threadIdx.y;
    int lane = threadIdx.x;
    float4 v = ((const float4*)(emb + (size_t)row * DDIM))[lane];
    float ss = v.x * v.x + v.y * v.y + v.z * v.z + v.w * v.w;
    #pragma unroll
    for (int o = 16; o; o >>= 1) ss += __shfl_xor_sync(0xFFFFFFFFu, ss, o);
    float inv = rsqrtf(fmaxf(ss, 1e-24f));
    inv = inv * (1.5f - 0.5f * ss * inv * inv);
    float z[4] = {v.x * inv, v.y * inv, v.z * inv, v.w * inv};
    __nv_bfloat16 h[4], l[4], h10[4], l10[4];
    #pragma unroll
    for (int k = 0; k < 4; k++) {
        h[k] = __float2bfloat16_rn(z[k]);
        l[k] = __float2bfloat16_rn(z[k] - __bfloat162float(h[k]));
        float z10 = z[k] * 10.0f;
        h10[k] = __float2bfloat16_rn(z10);
        l10[k] = __float2bfloat16_rn(z10 - __bfloat162float(h10[k]));
    }
    size_t base = (size_t)row * KTOT + lane * 4;
    *(uint2*)(g_za + base)       = *(uint2*)h10;
    *(uint2*)(g_za + base + 128) = *(uint2*)h10;
    *(uint2*)(g_za + base + 256) = *(uint2*)l10;
    *(uint2*)(g_zb + base)       = *(uint2*)h;
    *(uint2*)(g_zb + base + 128) = *(uint2*)l;
    *(uint2*)(g_zb + base + 256) = *(uint2*)h;
}

// ---- Kernel 2: upper-triangle tiles; GEMM + dual-anchor epilogue ----
__global__ void __launch_bounds__(256, 1)
main_kernel(const int* __restrict__ st, const int* __restrict__ cen) {
    extern __shared__ char smem[];
    const uint32_t sb = smem_u32(smem);
    const int tid   = threadIdx.x;
    const int wid   = tid >> 5;
    const int lane  = tid & 31;
    const int warpM = wid >> 1;
    const int warpN = wid & 1;

    // triangular decode: F(r) = r*64 - r*(r-1)/2; bx = max r with F(r) <= t
    const int t = blockIdx.x;
    int bx = (int)(64.5f - sqrtf(64.5f * 64.5f - 2.0f * (float)t));
    bx = bx < 0 ? 0 : (bx > 63 ? 63 : bx);
    #define FTRI(r) ((r) * NT - ((r) * ((r) - 1)) / 2)
    while (bx > 0 && FTRI(bx) > t) bx--;
    while (FTRI(bx + 1) <= t) bx++;
    const int by = bx + (t - FTRI(bx));
    const int rBase = bx * TM;
    const int cBase = by * TN;
    const bool isDiag = (bx == by);

    int* sTi   = (int*)(smem + SM_TI);
    int* sCenR = (int*)(smem + SM_CENR);
    int* sTj   = (int*)(smem + SM_TJ);
    int* sCenC = (int*)(smem + SM_CENC);
    if (tid < 128) {
        sTi[tid]   = st[rBase + tid];
        sCenR[tid] = cen[rBase + tid];
    } else {
        sTj[tid - 128]   = st[cBase + tid - 128];
        sCenC[tid - 128] = cen[cBase + tid - 128];
    }

    auto load_chunk = [&](int c) {
        uint32_t bA = sb + (c % 3) * SM_STAGE;
        uint32_t bB = bA + 16384;
        #pragma unroll
        for (int u = 0; u < 4; u++) {
            int idx = u * 256 + tid;
            int row = idx >> 3, cc = idx & 7;
            uint32_t sw = (uint32_t)row * 128 + (uint32_t)((cc ^ (row & 7)) << 4);
            cp16(bA + sw, g_za + (size_t)(rBase + row) * KTOT + c * KC + cc * 8);
            cp16(bB + sw, g_zb + (size_t)(cBase + row) * KTOT + c * KC + cc * 8);
        }
        cp_commit();
    };

    load_chunk(0);
    load_chunk(1);
    load_chunk(2);

    float acc[2][8][4];
    #pragma unroll
    for (int mf = 0; mf < 2; mf++)
        #pragma unroll
        for (int nf = 0; nf < 8; nf++)
            #pragma unroll
            for (int r = 0; r < 4; r++) acc[mf][nf][r] = 0.0f;

    const int trow = lane & 7;
    const int tg1  = (lane >> 3) & 1;
    const int cadd = lane >> 4;
    const int rowA0 = warpM * 32 + tg1 * 8 + trow;
    const int rowB0 = warpN * 64 + tg1 * 8 + trow;

    #pragma unroll
    for (int c = 0; c < 6; c++) {
        cp_wait<2>();
        __syncthreads();
        uint32_t bA = sb + (c % 3) * SM_STAGE;
        uint32_t bB = bA + 16384;

        #pragma unroll
        for (int kk = 0; kk < 4; kk++) {
            uint32_t aF[2][4], bF[4][4];
            #pragma unroll
            for (int mf = 0; mf < 2; mf++) {
                int row = rowA0 + mf * 16;
                uint32_t a = bA + row * 128 + (((kk * 2 + cadd) ^ (row & 7)) << 4);
                ldsm4(aF[mf][0], aF[mf][1], aF[mf][2], aF[mf][3], a);
            }
            #pragma unroll
            for (int np = 0; np < 4; np++) {
                int row = rowB0 + np * 16;
                uint32_t a = bB + row * 128 + (((kk * 2 + cadd) ^ (row & 7)) << 4);
                ldsm4(bF[np][0], bF[np][1], bF[np][2], bF[np][3], a);
            }
            #pragma unroll
            for (int mf = 0; mf < 2; mf++)
                #pragma unroll
                for (int np = 0; np < 4; np++) {
                    mma16816(acc[mf][np * 2][0], acc[mf][np * 2][1],
                             acc[mf][np * 2][2], acc[mf][np * 2][3],
                             aF[mf][0], aF[mf][1], aF[mf][2], aF[mf][3],
                             bF[np][0], bF[np][2]);
                    mma16816(acc[mf][np * 2 + 1][0], acc[mf][np * 2 + 1][1],
                             acc[mf][np * 2 + 1][2], acc[mf][np * 2 + 1][3],
                             aF[mf][0], aF[mf][1], aF[mf][2], aF[mf][3],
                             bF[np][1], bF[np][3]);
                }
        }
        __syncthreads();
        if (c + 3 < 6) load_chunk(c + 3); else cp_commit();
    }

    // ---------------- epilogue: acc holds 10*sim -> e = exp ----------------
    #pragma unroll
    for (int mf = 0; mf < 2; mf++)
        #pragma unroll
        for (int nf = 0; nf < 8; nf++)
            #pragma unroll
            for (int r = 0; r < 4; r++) acc[mf][nf][r] = __expf(acc[mf][nf][r]);

    const int q  = lane >> 2;
    const int c2 = (lane & 3) * 2;
    int lr[4], rti[4], rcen[4];
    #pragma unroll
    for (int u = 0; u < 4; u++) {
        lr[u]   = warpM * 32 + ((u & 1) ? 8 : 0) + ((u >> 1) ? 16 : 0) + q;
        rti[u]  = sTi[lr[u]];
        rcen[u] = sCenR[lr[u]];
    }

    // ---- row-anchored pass ----
    #pragma unroll
    for (int u = 0; u < 4; u++) {
        const int mf = u >> 1;
        const int rb = (u & 1) * 2;
        float sa = 0.f, sp = 0.f;
        #pragma unroll
        for (int nf = 0; nf < 8; nf++) {
            #pragma unroll
            for (int cc = 0; cc < 2; cc++) {
                int lc = warpN * 64 + nf * 8 + c2 + cc;
                float e = acc[mf][nf][rb + cc];
                int td = rti[u] - sTj[lc];
                td = td < 0 ? -td : td;
                bool self = isDiag && (lc == lr[u]);
                if (!self) {
                    sa += e;
                    if (rcen[u] && td < TTHRESH) sp += e;
                }
            }
        }
        #pragma unroll
        for (int o = 1; o <= 2; o <<= 1) {
            sa += __shfl_xor_sync(0xFFFFFFFFu, sa, o);
            sp += __shfl_xor_sync(0xFFFFFFFFu, sp, o);
        }
        if ((lane & 3) == 0)
            g_part[(size_t)(rBase + lr[u]) * NSEG + 2 * by + warpN] =
                make_float2(sa, sp);
    }

    // ---- col-anchored pass (off-diagonal tiles only) ----
    if (!isDiag) {
        float2* colp = (float2*)(smem + SM_COLP);   // [4 warpM][128 cols]
        #pragma unroll
        for (int nf = 0; nf < 8; nf++) {
            int lc0 = warpN * 64 + nf * 8 + c2;
            int tj0 = sTj[lc0], tj1 = sTj[lc0 + 1];
            int cc0 = sCenC[lc0], cc1 = sCenC[lc0 + 1];
            float ca0 = 0.f, cp0 = 0.f, ca1 = 0.f, cp1 = 0.f;
            #pragma unroll
            for (int u = 0; u < 4; u++) {
                const int mf = u >> 1;
                const int rb = (u & 1) * 2;
                float e0 = acc[mf][nf][rb];
                float e1 = acc[mf][nf][rb + 1];
                int td0 = rti[u] - tj0; td0 = td0 < 0 ? -td0 : td0;
                int td1 = rti[u] - tj1; td1 = td1 < 0 ? -td1 : td1;
                ca0 += e0;
                ca1 += e1;
                if (cc0 && td0 < TTHRESH) cp0 += e0;
                if (cc1 && td1 < TTHRESH) cp1 += e1;
            }
            #pragma unroll
            for (int o = 4; o <= 16; o <<= 1) {
                ca0 += __shfl_xor_sync(0xFFFFFFFFu, ca0, o);
                cp0 += __shfl_xor_sync(0xFFFFFFFFu, cp0, o);
                ca1 += __shfl_xor_sync(0xFFFFFFFFu, ca1, o);
                cp1 += __shfl_xor_sync(0xFFFFFFFFu, cp1, o);
            }
            if (q == 0) {
                colp[warpM * 128 + lc0]     = make_float2(ca0, cp0);
                colp[warpM * 128 + lc0 + 1] = make_float2(ca1, cp1);
            }
        }
        __syncthreads();
        // combine warpM pairs -> M halves, write col-anchored partials
        const int mhalf = tid >> 7;
        const int col   = tid & 127;
        float2 v0 = colp[(2 * mhalf) * 128 + col];
        float2 v1 = colp[(2 * mhalf + 1) * 128 + col];
        g_part[(size_t)(cBase + col) * NSEG + 2 * bx + mhalf] =
            make_float2(v0.x + v1.x, v0.y + v1.y);
    }
}

// ---- Kernel 3: per-row merge + block partial reduction ----
__global__ void combine_kernel() {
    __shared__ float sh_s[256], sh_c[256];
    int tid = threadIdx.x;
    int row = blockIdx.x * 256 + tid;
    float sa = 0.0f, sp = 0.0f;
    const float4* p = (const float4*)(g_part + (size_t)row * NSEG);
    #pragma unroll
    for (int s = 0; s < NSEG / 2; s++) {
        float4 v = p[s];
        sa += v.x + v.z;
        sp += v.y + v.w;
    }
    float pr = 0.0f, c = 0.0f;
    if (sp > 0.0f) { pr = logf(sa) - logf(sp); c = 1.0f; }
    sh_s[tid] = pr; sh_c[tid] = c;
    __syncthreads();
    #pragma unroll
    for (int o = 128; o > 0; o >>= 1) {
        if (tid < o) { sh_s[tid] += sh_s[tid + o]; sh_c[tid] += sh_c[tid + o]; }
        __syncthreads();
    }
    if (tid == 0) { g_bsum[blockIdx.x] = sh_s[0]; g_bcnt[blockIdx.x] = sh_c[0]; }
}

__global__ void final_kernel(float* __restrict__ out) {
    int lane = threadIdx.x;
    float s = g_bsum[lane], c = g_bcnt[lane];
    #pragma unroll
    for (int o = 16; o; o >>= 1) {
        s += __shfl_xor_sync(0xFFFFFFFFu, s, o);
        c += __shfl_xor_sync(0xFFFFFFFFu, c, o);
    }
    if (lane == 0) out[0] = (c > 0.0f) ? (s / c) : 0.0f;
}

extern "C" void kernel_launch(void* const* d_in, const int* in_sizes, int n_in,
                              void* d_out, int out_size) {
    const float* emb = (const float*)d_in[0];
    const int*   st  = (const int*)d_in[1];
    const int*   cn  = (const int*)d_in[2];
    float* out = (float*)d_out;

    cudaFuncSetAttribute(main_kernel, cudaFuncAttributeMaxDynamicSharedMemorySize,
                         SMEM_TOTAL);

    norm_kernel<<<BDIM / 8, dim3(32, 8)>>>(emb);
    main_kernel<<<(NT * (NT + 1)) / 2, 256, SMEM_TOTAL>>>(st, cn);
    combine_kernel<<<BDIM / 256, 256>>>();
    final_kernel<<<1, 32>>>(out);
}

// round 5
// speedup vs baseline: 5.1935x; 1.4216x over previous
#include <cuda_runtime.h>
#include <cuda_bf16.h>
#include <cstdint>

// B=8192, D=128. sim = (Z Z^T)/0.1 with masked logsumexps -> scalar mean.
// bf16 hi/lo split folded into one K=384 GEMM on mma.sync:
//   A = [10*z_hi | 10*z_hi | 10*z_lo],  Bt = [z_hi | z_lo | z_hi]
// Symmetry: only upper-triangle tiles (2080 of 4096); off-diag tiles emit
// both row-anchored and col-anchored partial sums.
// This round: 2-stage pipeline + __launch_bounds__(256,2) to guarantee
// 2 CTAs/SM (regs <= 128, smem 71.7KB/CTA).
#define BDIM 8192
#define DDIM 128
#define KTOT 384
#define TM   128
#define TN   128
#define KC   64
#define NSEG 128
#define NT   64
#define TTHRESH 365

__device__ __nv_bfloat16 g_za[BDIM * KTOT];   // 6MB
__device__ __nv_bfloat16 g_zb[BDIM * KTOT];   // 6MB
__device__ float2 g_part[BDIM * NSEG];        // 8MB
__device__ float  g_bsum[BDIM / 256];
__device__ float  g_bcnt[BDIM / 256];

// ---------------- PTX helpers (sm_80-portable only) ----------------
__device__ __forceinline__ uint32_t smem_u32(const void* p) {
    uint32_t a;
    asm("{ .reg .u64 t; cvta.to.shared.u64 t, %1; cvt.u32.u64 %0, t; }" : "=r"(a) : "l"(p));
    return a;
}
__device__ __forceinline__ void cp16(uint32_t dst, const void* src) {
    asm volatile("cp.async.cg.shared.global [%0], [%1], 16;" :: "r"(dst), "l"(src));
}
__device__ __forceinline__ void cp_commit() {
    asm volatile("cp.async.commit_group;" ::: "memory");
}
template <int N> __device__ __forceinline__ void cp_wait() {
    asm volatile("cp.async.wait_group %0;" :: "n"(N) : "memory");
}
__device__ __forceinline__ void ldsm4(uint32_t& r0, uint32_t& r1, uint32_t& r2,
                                      uint32_t& r3, uint32_t addr) {
    asm volatile("ldmatrix.sync.aligned.m8n8.x4.shared.b16 {%0,%1,%2,%3}, [%4];"
                 : "=r"(r0), "=r"(r1), "=r"(r2), "=r"(r3) : "r"(addr));
}
__device__ __forceinline__ void mma16816(float& d0, float& d1, float& d2, float& d3,
                                         uint32_t a0, uint32_t a1, uint32_t a2,
                                         uint32_t a3, uint32_t b0, uint32_t b1) {
    asm volatile(
        "mma.sync.aligned.m16n8k16.row.col.f32.bf16.bf16.f32 "
        "{%0,%1,%2,%3}, {%4,%5,%6,%7}, {%8,%9}, {%0,%1,%2,%3};"
        : "+f"(d0), "+f"(d1), "+f"(d2), "+f"(d3)
        : "r"(a0), "r"(a1), "r"(a2), "r"(a3), "r"(b0), "r"(b1));
}

// SMEM: 2 stages x (A 16K + B 16K) | colp 4K | ti/cenR/tj/cenC 4x512
#define SM_STAGE 32768
#define SM_COLP  65536
#define SM_TI    69632
#define SM_CENR  70144
#define SM_TJ    70656
#define SM_CENC  71168
#define SMEM_TOTAL 71680

// ---- Kernel 1: normalize + bf16 hi/lo split, K=384 layouts ----
__global__ void norm_kernel(const float* __restrict__ emb) {
    int row  = blockIdx.x * 8 + threadIdx.y;
    int lane = threadIdx.x;
    float4 v = ((const float4*)(emb + (size_t)row * DDIM))[lane];
    float ss = v.x * v.x + v.y * v.y + v.z * v.z + v.w * v.w;
    #pragma unroll
    for (int o = 16; o; o >>= 1) ss += __shfl_xor_sync(0xFFFFFFFFu, ss, o);
    float inv = rsqrtf(fmaxf(ss, 1e-24f));
    inv = inv * (1.5f - 0.5f * ss * inv * inv);
    float z[4] = {v.x * inv, v.y * inv, v.z * inv, v.w * inv};
    __nv_bfloat16 h[4], l[4], h10[4], l10[4];
    #pragma unroll
    for (int k = 0; k < 4; k++) {
        h[k] = __float2bfloat16_rn(z[k]);
        l[k] = __float2bfloat16_rn(z[k] - __bfloat162float(h[k]));
        float z10 = z[k] * 10.0f;
        h10[k] = __float2bfloat16_rn(z10);
        l10[k] = __float2bfloat16_rn(z10 - __bfloat162float(h10[k]));
    }
    size_t base = (size_t)row * KTOT + lane * 4;
    *(uint2*)(g_za + base)       = *(uint2*)h10;
    *(uint2*)(g_za + base + 128) = *(uint2*)h10;
    *(uint2*)(g_za + base + 256) = *(uint2*)l10;
    *(uint2*)(g_zb + base)       = *(uint2*)h;
    *(uint2*)(g_zb + base + 128) = *(uint2*)l;
    *(uint2*)(g_zb + base + 256) = *(uint2*)h;
}

// ---- Kernel 2: upper-triangle tiles; GEMM + dual-anchor epilogue ----
__global__ void __launch_bounds__(256, 2)
main_kernel(const int* __restrict__ st, const int* __restrict__ cen) {
    extern __shared__ char smem[];
    const uint32_t sb = smem_u32(smem);
    const int tid   = threadIdx.x;
    const int wid   = tid >> 5;
    const int lane  = tid & 31;
    const int warpM = wid >> 1;
    const int warpN = wid & 1;

    // triangular decode: F(r) = r*64 - r*(r-1)/2; bx = max r with F(r) <= t
    const int t = blockIdx.x;
    int bx = (int)(64.5f - sqrtf(64.5f * 64.5f - 2.0f * (float)t));
    bx = bx < 0 ? 0 : (bx > 63 ? 63 : bx);
    #define FTRI(r) ((r) * NT - ((r) * ((r) - 1)) / 2)
    while (bx > 0 && FTRI(bx) > t) bx--;
    while (FTRI(bx + 1) <= t) bx++;
    const int by = bx + (t - FTRI(bx));
    const int rBase = bx * TM;
    const int cBase = by * TN;
    const bool isDiag = (bx == by);

    int* sTi   = (int*)(smem + SM_TI);
    int* sCenR = (int*)(smem + SM_CENR);
    int* sTj   = (int*)(smem + SM_TJ);
    int* sCenC = (int*)(smem + SM_CENC);
    if (tid < 128) {
        sTi[tid]   = st[rBase + tid];
        sCenR[tid] = cen[rBase + tid];
    } else {
        sTj[tid - 128]   = st[cBase + tid - 128];
        sCenC[tid - 128] = cen[cBase + tid - 128];
    }

    auto load_chunk = [&](int c) {
        uint32_t bA = sb + (c & 1) * SM_STAGE;
        uint32_t bB = bA + 16384;
        #pragma unroll
        for (int u = 0; u < 4; u++) {
            int idx = u * 256 + tid;
            int row = idx >> 3, cc = idx & 7;
            uint32_t sw = (uint32_t)row * 128 + (uint32_t)((cc ^ (row & 7)) << 4);
            cp16(bA + sw, g_za + (size_t)(rBase + row) * KTOT + c * KC + cc * 8);
            cp16(bB + sw, g_zb + (size_t)(cBase + row) * KTOT + c * KC + cc * 8);
        }
        cp_commit();
    };

    load_chunk(0);
    load_chunk(1);

    float acc[2][8][4];
    #pragma unroll
    for (int mf = 0; mf < 2; mf++)
        #pragma unroll
        for (int nf = 0; nf < 8; nf++)
            #pragma unroll
            for (int r = 0; r < 4; r++) acc[mf][nf][r] = 0.0f;

    const int trow = lane & 7;
    const int tg1  = (lane >> 3) & 1;
    const int cadd = lane >> 4;
    const int rowA0 = warpM * 32 + tg1 * 8 + trow;
    const int rowB0 = warpN * 64 + tg1 * 8 + trow;

    #pragma unroll
    for (int c = 0; c < 6; c++) {
        if (c < 5) cp_wait<1>(); else cp_wait<0>();
        __syncthreads();
        uint32_t bA = sb + (c & 1) * SM_STAGE;
        uint32_t bB = bA + 16384;

        #pragma unroll
        for (int kk = 0; kk < 4; kk++) {
            uint32_t aF[2][4], bF[4][4];
            #pragma unroll
            for (int mf = 0; mf < 2; mf++) {
                int row = rowA0 + mf * 16;
                uint32_t a = bA + row * 128 + (((kk * 2 + cadd) ^ (row & 7)) << 4);
                ldsm4(aF[mf][0], aF[mf][1], aF[mf][2], aF[mf][3], a);
            }
            #pragma unroll
            for (int np = 0; np < 4; np++) {
                int row = rowB0 + np * 16;
                uint32_t a = bB + row * 128 + (((kk * 2 + cadd) ^ (row & 7)) << 4);
                ldsm4(bF[np][0], bF[np][1], bF[np][2], bF[np][3], a);
            }
            #pragma unroll
            for (int mf = 0; mf < 2; mf++)
                #pragma unroll
                for (int np = 0; np < 4; np++) {
                    mma16816(acc[mf][np * 2][0], acc[mf][np * 2][1],
                             acc[mf][np * 2][2], acc[mf][np * 2][3],
                             aF[mf][0], aF[mf][1], aF[mf][2], aF[mf][3],
                             bF[np][0], bF[np][2]);
                    mma16816(acc[mf][np * 2 + 1][0], acc[mf][np * 2 + 1][1],
                             acc[mf][np * 2 + 1][2], acc[mf][np * 2 + 1][3],
                             aF[mf][0], aF[mf][1], aF[mf][2], aF[mf][3],
                             bF[np][1], bF[np][3]);
                }
        }
        __syncthreads();
        if (c + 2 < 6) load_chunk(c + 2);
    }

    // ---------------- epilogue: acc holds 10*sim -> e = exp ----------------
    #pragma unroll
    for (int mf = 0; mf < 2; mf++)
        #pragma unroll
        for (int nf = 0; nf < 8; nf++)
            #pragma unroll
            for (int r = 0; r < 4; r++) acc[mf][nf][r] = __expf(acc[mf][nf][r]);

    const int q  = lane >> 2;
    const int c2 = (lane & 3) * 2;

    // ---- row-anchored pass ----
    #pragma unroll
    for (int u = 0; u < 4; u++) {
        const int mf = u >> 1;
        const int rb = (u & 1) * 2;
        const int lrow = warpM * 32 + mf * 16 + (u & 1) * 8 + q;
        const int ti = sTi[lrow];
        const int rc = sCenR[lrow];
        float sa = 0.f, sp = 0.f;
        #pragma unroll
        for (int nf = 0; nf < 8; nf++) {
            #pragma unroll
            for (int cc = 0; cc < 2; cc++) {
                int lc = warpN * 64 + nf * 8 + c2 + cc;
                float e = acc[mf][nf][rb + cc];
                int td = ti - sTj[lc];
                td = td < 0 ? -td : td;
                bool self = isDiag && (lc == lrow);
                if (!self) {
                    sa += e;
                    if (rc && td < TTHRESH) sp += e;
                }
            }
        }
        #pragma unroll
        for (int o = 1; o <= 2; o <<= 1) {
            sa += __shfl_xor_sync(0xFFFFFFFFu, sa, o);
            sp += __shfl_xor_sync(0xFFFFFFFFu, sp, o);
        }
        if ((lane & 3) == 0)
            g_part[(size_t)(rBase + lrow) * NSEG + 2 * by + warpN] =
                make_float2(sa, sp);
    }

    // ---- col-anchored pass (off-diagonal tiles only) ----
    if (!isDiag) {
        float2* colp = (float2*)(smem + SM_COLP);   // [4 warpM][128 cols]
        const int ti0 = sTi[warpM * 32 + q];
        const int ti1 = sTi[warpM * 32 + 8 + q];
        const int ti2 = sTi[warpM * 32 + 16 + q];
        const int ti3 = sTi[warpM * 32 + 24 + q];
        #pragma unroll
        for (int nf = 0; nf < 8; nf++) {
            int lc0 = warpN * 64 + nf * 8 + c2;
            int tj0 = sTj[lc0], tj1 = sTj[lc0 + 1];
            int cc0 = sCenC[lc0], cc1 = sCenC[lc0 + 1];
            float ca0 = 0.f, cp0 = 0.f, ca1 = 0.f, cp1 = 0.f;
            #pragma unroll
            for (int u = 0; u < 4; u++) {
                const int mf = u >> 1;
                const int rb = (u & 1) * 2;
                const int ti = (u == 0) ? ti0 : (u == 1) ? ti1 : (u == 2) ? ti2 : ti3;
                float e0 = acc[mf][nf][rb];
                float e1 = acc[mf][nf][rb + 1];
                int td0 = ti - tj0; td0 = td0 < 0 ? -td0 : td0;
                int td1 = ti - tj1; td1 = td1 < 0 ? -td1 : td1;
                ca0 += e0;
                ca1 += e1;
                if (cc0 && td0 < TTHRESH) cp0 += e0;
                if (cc1 && td1 < TTHRESH) cp1 += e1;
            }
            #pragma unroll
            for (int o = 4; o <= 16; o <<= 1) {
                ca0 += __shfl_xor_sync(0xFFFFFFFFu, ca0, o);
                cp0 += __shfl_xor_sync(0xFFFFFFFFu, cp0, o);
                ca1 += __shfl_xor_sync(0xFFFFFFFFu, ca1, o);
                cp1 += __shfl_xor_sync(0xFFFFFFFFu, cp1, o);
            }
            if (q == 0) {
                colp[warpM * 128 + lc0]     = make_float2(ca0, cp0);
                colp[warpM * 128 + lc0 + 1] = make_float2(ca1, cp1);
            }
        }
        __syncthreads();
        const int mhalf = tid >> 7;
        const int col   = tid & 127;
        float2 v0 = colp[(2 * mhalf) * 128 + col];
        float2 v1 = colp[(2 * mhalf + 1) * 128 + col];
        g_part[(size_t)(cBase + col) * NSEG + 2 * bx + mhalf] =
            make_float2(v0.x + v1.x, v0.y + v1.y);
    }
}

// ---- Kernel 3: per-row merge + block partial reduction ----
__global__ void combine_kernel() {
    __shared__ float sh_s[256], sh_c[256];
    int tid = threadIdx.x;
    int row = blockIdx.x * 256 + tid;
    float sa = 0.0f, sp = 0.0f;
    const float4* p = (const float4*)(g_part + (size_t)row * NSEG);
    #pragma unroll
    for (int s = 0; s < NSEG / 2; s++) {
        float4 v = p[s];
        sa += v.x + v.z;
        sp += v.y + v.w;
    }
    float pr = 0.0f, c = 0.0f;
    if (sp > 0.0f) { pr = logf(sa) - logf(sp); c = 1.0f; }
    sh_s[tid] = pr; sh_c[tid] = c;
    __syncthreads();
    #pragma unroll
    for (int o = 128; o > 0; o >>= 1) {
        if (tid < o) { sh_s[tid] += sh_s[tid + o]; sh_c[tid] += sh_c[tid + o]; }
        __syncthreads();
    }
    if (tid == 0) { g_bsum[blockIdx.x] = sh_s[0]; g_bcnt[blockIdx.x] = sh_c[0]; }
}

__global__ void final_kernel(float* __restrict__ out) {
    int lane = threadIdx.x;
    float s = g_bsum[lane], c = g_bcnt[lane];
    #pragma unroll
    for (int o = 16; o; o >>= 1) {
        s += __shfl_xor_sync(0xFFFFFFFFu, s, o);
        c += __shfl_xor_sync(0xFFFFFFFFu, c, o);
    }
    if (lane == 0) out[0] = (c > 0.0f) ? (s / c) : 0.0f;
}

extern "C" void kernel_launch(void* const* d_in, const int* in_sizes, int n_in,
                              void* d_out, int out_size) {
    const float* emb = (const float*)d_in[0];
    const int*   st  = (const int*)d_in[1];
    const int*   cn  = (const int*)d_in[2];
    float* out = (float*)d_out;

    cudaFuncSetAttribute(main_kernel, cudaFuncAttributeMaxDynamicSharedMemorySize,
                         SMEM_TOTAL);

    norm_kernel<<<BDIM / 8, dim3(32, 8)>>>(emb);
    main_kernel<<<(NT * (NT + 1)) / 2, 256, SMEM_TOTAL>>>(st, cn);
    combine_kernel<<<BDIM / 256, 256>>>();
    final_kernel<<<1, 32>>>(out);
}

// round 6
// speedup vs baseline: 6.2752x; 1.2083x over previous
#include <cuda_runtime.h>
#include <cuda_bf16.h>
#include <cstdint>

// B=8192, D=128. sim = (Z Z^T)/0.1 with masked logsumexps -> scalar mean.
// bf16 split GEMM on mma.sync, K=256 effective:
//   A = [10*z_hi | 10*z_lo],  B = [z_hi] (reused for both A halves)
//   computed logit = 10*(h.h + l.h); dropped 10*h_i.l_j ~ 1.5e-3 noise.
// Symmetry: upper-triangle tiles only; dual-anchor (row+col) partial sums.
#define BDIM 8192
#define DDIM 128
#define KA   256
#define KB   128
#define TM   128
#define TN   128
#define KC   64
#define NSEG 128
#define NT   64
#define TTHRESH 365

__device__ __nv_bfloat16 g_za[BDIM * KA];     // 4MB: [10h | 10l]
__device__ __nv_bfloat16 g_zb[BDIM * KB];     // 2MB: [h]
__device__ float2 g_part[BDIM * NSEG];        // 8MB
__device__ float  g_bsum[BDIM / 256];
__device__ float  g_bcnt[BDIM / 256];

// ---------------- PTX helpers (sm_80-portable only) ----------------
__device__ __forceinline__ uint32_t smem_u32(const void* p) {
    uint32_t a;
    asm("{ .reg .u64 t; cvta.to.shared.u64 t, %1; cvt.u32.u64 %0, t; }" : "=r"(a) : "l"(p));
    return a;
}
__device__ __forceinline__ void cp16(uint32_t dst, const void* src) {
    asm volatile("cp.async.cg.shared.global [%0], [%1], 16;" :: "r"(dst), "l"(src));
}
__device__ __forceinline__ void cp_commit() {
    asm volatile("cp.async.commit_group;" ::: "memory");
}
template <int N> __device__ __forceinline__ void cp_wait() {
    asm volatile("cp.async.wait_group %0;" :: "n"(N) : "memory");
}
__device__ __forceinline__ void ldsm4(uint32_t& r0, uint32_t& r1, uint32_t& r2,
                                      uint32_t& r3, uint32_t addr) {
    asm volatile("ldmatrix.sync.aligned.m8n8.x4.shared.b16 {%0,%1,%2,%3}, [%4];"
                 : "=r"(r0), "=r"(r1), "=r"(r2), "=r"(r3) : "r"(addr));
}
__device__ __forceinline__ void mma16816(float& d0, float& d1, float& d2, float& d3,
                                         uint32_t a0, uint32_t a1, uint32_t a2,
                                         uint32_t a3, uint32_t b0, uint32_t b1) {
    asm volatile(
        "mma.sync.aligned.m16n8k16.row.col.f32.bf16.bf16.f32 "
        "{%0,%1,%2,%3}, {%4,%5,%6,%7}, {%8,%9}, {%0,%1,%2,%3};"
        : "+f"(d0), "+f"(d1), "+f"(d2), "+f"(d3)
        : "r"(a0), "r"(a1), "r"(a2), "r"(a3), "r"(b0), "r"(b1));
}

// SMEM: 2 stages x (A 16K + B 16K) | colp 4K | ti/cenR/tj/cenC 4x512
#define SM_STAGE 32768
#define SM_COLP  65536
#define SM_TI    69632
#define SM_CENR  70144
#define SM_TJ    70656
#define SM_CENC  71168
#define SMEM_TOTAL 71680

// ---- Kernel 1: normalize + bf16 hi/lo split ----
__global__ void norm_kernel(const float* __restrict__ emb) {
    int row  = blockIdx.x * 8 + threadIdx.y;
    int lane = threadIdx.x;
    float4 v = ((const float4*)(emb + (size_t)row * DDIM))[lane];
    float ss = v.x * v.x + v.y * v.y + v.z * v.z + v.w * v.w;
    #pragma unroll
    for (int o = 16; o; o >>= 1) ss += __shfl_xor_sync(0xFFFFFFFFu, ss, o);
    float inv = rsqrtf(fmaxf(ss, 1e-24f));
    inv = inv * (1.5f - 0.5f * ss * inv * inv);
    float z[4] = {v.x * inv, v.y * inv, v.z * inv, v.w * inv};
    __nv_bfloat16 h[4], h10[4], l10[4];
    #pragma unroll
    for (int k = 0; k < 4; k++) {
        h[k] = __float2bfloat16_rn(z[k]);
        float z10 = z[k] * 10.0f;
        h10[k] = __float2bfloat16_rn(z10);
        l10[k] = __float2bfloat16_rn(z10 - __bfloat162float(h10[k]));
    }
    size_t ba = (size_t)row * KA + lane * 4;
    size_t bb = (size_t)row * KB + lane * 4;
    *(uint2*)(g_za + ba)       = *(uint2*)h10;
    *(uint2*)(g_za + ba + 128) = *(uint2*)l10;
    *(uint2*)(g_zb + bb)       = *(uint2*)h;
}

// ---- Kernel 2: upper-triangle tiles; GEMM + dual-anchor epilogue ----
__global__ void __launch_bounds__(256, 2)
main_kernel(const int* __restrict__ st, const int* __restrict__ cen) {
    extern __shared__ char smem[];
    const uint32_t sb = smem_u32(smem);
    const int tid   = threadIdx.x;
    const int wid   = tid >> 5;
    const int lane  = tid & 31;
    const int warpM = wid >> 1;
    const int warpN = wid & 1;

    // triangular decode
    const int t = blockIdx.x;
    int bx = (int)(64.5f - sqrtf(64.5f * 64.5f - 2.0f * (float)t));
    bx = bx < 0 ? 0 : (bx > 63 ? 63 : bx);
    #define FTRI(r) ((r) * NT - ((r) * ((r) - 1)) / 2)
    while (bx > 0 && FTRI(bx) > t) bx--;
    while (FTRI(bx + 1) <= t) bx++;
    const int by = bx + (t - FTRI(bx));
    const int rBase = bx * TM;
    const int cBase = by * TN;
    const bool isDiag = (bx == by);

    int* sTi   = (int*)(smem + SM_TI);
    int* sCenR = (int*)(smem + SM_CENR);
    int* sTj   = (int*)(smem + SM_TJ);
    int* sCenC = (int*)(smem + SM_CENC);
    if (tid < 128) {
        sTi[tid]   = st[rBase + tid];
        sCenR[tid] = cen[rBase + tid];
    } else {
        sTj[tid - 128]   = st[cBase + tid - 128];
        sCenC[tid - 128] = cen[cBase + tid - 128];
    }

    // A chunk c: g_za K-offset c*64 (0..255). B chunk: (c&1)*64 within K=128.
    auto load_chunk = [&](int c) {
        uint32_t bA = sb + (c & 1) * SM_STAGE;
        uint32_t bB = bA + 16384;
        #pragma unroll
        for (int u = 0; u < 4; u++) {
            int idx = u * 256 + tid;
            int row = idx >> 3, cc = idx & 7;
            uint32_t sw = (uint32_t)row * 128 + (uint32_t)((cc ^ (row & 7)) << 4);
            cp16(bA + sw, g_za + (size_t)(rBase + row) * KA + c * KC + cc * 8);
            cp16(bB + sw, g_zb + (size_t)(cBase + row) * KB + (c & 1) * KC + cc * 8);
        }
        cp_commit();
    };

    load_chunk(0);
    load_chunk(1);

    float acc[2][8][4];
    #pragma unroll
    for (int mf = 0; mf < 2; mf++)
        #pragma unroll
        for (int nf = 0; nf < 8; nf++)
            #pragma unroll
            for (int r = 0; r < 4; r++) acc[mf][nf][r] = 0.0f;

    const int trow = lane & 7;
    const int tg1  = (lane >> 3) & 1;
    const int cadd = lane >> 4;
    const int rowA0 = warpM * 32 + tg1 * 8 + trow;
    const int rowB0 = warpN * 64 + tg1 * 8 + trow;

    #pragma unroll
    for (int c = 0; c < 4; c++) {
        if (c < 3) cp_wait<1>(); else cp_wait<0>();
        __syncthreads();
        uint32_t bA = sb + (c & 1) * SM_STAGE;
        uint32_t bB = bA + 16384;

        #pragma unroll
        for (int kk = 0; kk < 4; kk++) {
            uint32_t aF[2][4], bF[4][4];
            #pragma unroll
            for (int mf = 0; mf < 2; mf++) {
                int row = rowA0 + mf * 16;
                uint32_t a = bA + row * 128 + (((kk * 2 + cadd) ^ (row & 7)) << 4);
                ldsm4(aF[mf][0], aF[mf][1], aF[mf][2], aF[mf][3], a);
            }
            #pragma unroll
            for (int np = 0; np < 4; np++) {
                int row = rowB0 + np * 16;
                uint32_t a = bB + row * 128 + (((kk * 2 + cadd) ^ (row & 7)) << 4);
                ldsm4(bF[np][0], bF[np][1], bF[np][2], bF[np][3], a);
            }
            #pragma unroll
            for (int mf = 0; mf < 2; mf++)
                #pragma unroll
                for (int np = 0; np < 4; np++) {
                    mma16816(acc[mf][np * 2][0], acc[mf][np * 2][1],
                             acc[mf][np * 2][2], acc[mf][np * 2][3],
                             aF[mf][0], aF[mf][1], aF[mf][2], aF[mf][3],
                             bF[np][0], bF[np][2]);
                    mma16816(acc[mf][np * 2 + 1][0], acc[mf][np * 2 + 1][1],
                             acc[mf][np * 2 + 1][2], acc[mf][np * 2 + 1][3],
                             aF[mf][0], aF[mf][1], aF[mf][2], aF[mf][3],
                             bF[np][1], bF[np][3]);
                }
        }
        __syncthreads();
        if (c + 2 < 4) load_chunk(c + 2);
    }

    // ---------------- epilogue: acc holds 10*sim -> e = exp ----------------
    #pragma unroll
    for (int mf = 0; mf < 2; mf++)
        #pragma unroll
        for (int nf = 0; nf < 8; nf++)
            #pragma unroll
            for (int r = 0; r < 4; r++) acc[mf][nf][r] = __expf(acc[mf][nf][r]);

    const int q  = lane >> 2;
    const int c2 = (lane & 3) * 2;

    // ---- row-anchored pass ----
    #pragma unroll
    for (int u = 0; u < 4; u++) {
        const int mf = u >> 1;
        const int rb = (u & 1) * 2;
        const int lrow = warpM * 32 + mf * 16 + (u & 1) * 8 + q;
        const int ti = sTi[lrow];
        const int rc = sCenR[lrow];
        float sa = 0.f, sp = 0.f;
        #pragma unroll
        for (int nf = 0; nf < 8; nf++) {
            #pragma unroll
            for (int cc = 0; cc < 2; cc++) {
                int lc = warpN * 64 + nf * 8 + c2 + cc;
                float e = acc[mf][nf][rb + cc];
                int td = ti - sTj[lc];
                td = td < 0 ? -td : td;
                bool self = isDiag && (lc == lrow);
                if (!self) {
                    sa += e;
                    if (rc && td < TTHRESH) sp += e;
                }
            }
        }
        #pragma unroll
        for (int o = 1; o <= 2; o <<= 1) {
            sa += __shfl_xor_sync(0xFFFFFFFFu, sa, o);
            sp += __shfl_xor_sync(0xFFFFFFFFu, sp, o);
        }
        if ((lane & 3) == 0)
            g_part[(size_t)(rBase + lrow) * NSEG + 2 * by + warpN] =
                make_float2(sa, sp);
    }

    // ---- col-anchored pass (off-diagonal tiles only) ----
    if (!isDiag) {
        float2* colp = (float2*)(smem + SM_COLP);
        const int ti0 = sTi[warpM * 32 + q];
        const int ti1 = sTi[warpM * 32 + 8 + q];
        const int ti2 = sTi[warpM * 32 + 16 + q];
        const int ti3 = sTi[warpM * 32 + 24 + q];
        #pragma unroll
        for (int nf = 0; nf < 8; nf++) {
            int lc0 = warpN * 64 + nf * 8 + c2;
            int tj0 = sTj[lc0], tj1 = sTj[lc0 + 1];
            int cc0 = sCenC[lc0], cc1 = sCenC[lc0 + 1];
            float ca0 = 0.f, cp0 = 0.f, ca1 = 0.f, cp1 = 0.f;
            #pragma unroll
            for (int u = 0; u < 4; u++) {
                const int mf = u >> 1;
                const int rb = (u & 1) * 2;
                const int ti = (u == 0) ? ti0 : (u == 1) ? ti1 : (u == 2) ? ti2 : ti3;
                float e0 = acc[mf][nf][rb];
                float e1 = acc[mf][nf][rb + 1];
                int td0 = ti - tj0; td0 = td0 < 0 ? -td0 : td0;
                int td1 = ti - tj1; td1 = td1 < 0 ? -td1 : td1;
                ca0 += e0;
                ca1 += e1;
                if (cc0 && td0 < TTHRESH) cp0 += e0;
                if (cc1 && td1 < TTHRESH) cp1 += e1;
            }
            #pragma unroll
            for (int o = 4; o <= 16; o <<= 1) {
                ca0 += __shfl_xor_sync(0xFFFFFFFFu, ca0, o);
                cp0 += __shfl_xor_sync(0xFFFFFFFFu, cp0, o);
                ca1 += __shfl_xor_sync(0xFFFFFFFFu, ca1, o);
                cp1 += __shfl_xor_sync(0xFFFFFFFFu, cp1, o);
            }
            if (q == 0) {
                colp[warpM * 128 + lc0]     = make_float2(ca0, cp0);
                colp[warpM * 128 + lc0 + 1] = make_float2(ca1, cp1);
            }
        }
        __syncthreads();
        const int mhalf = tid >> 7;
        const int col   = tid & 127;
        float2 v0 = colp[(2 * mhalf) * 128 + col];
        float2 v1 = colp[(2 * mhalf + 1) * 128 + col];
        g_part[(size_t)(cBase + col) * NSEG + 2 * bx + mhalf] =
            make_float2(v0.x + v1.x, v0.y + v1.y);
    }
}

// ---- Kernel 3: per-row merge + block partial reduction ----
__global__ void combine_kernel() {
    __shared__ float sh_s[256], sh_c[256];
    int tid = threadIdx.x;
    int row = blockIdx.x * 256 + tid;
    float sa = 0.0f, sp = 0.0f;
    const float4* p = (const float4*)(g_part + (size_t)row * NSEG);
    #pragma unroll
    for (int s = 0; s < NSEG / 2; s++) {
        float4 v = p[s];
        sa += v.x + v.z;
        sp += v.y + v.w;
    }
    float pr = 0.0f, c = 0.0f;
    if (sp > 0.0f) { pr = logf(sa) - logf(sp); c = 1.0f; }
    sh_s[tid] = pr; sh_c[tid] = c;
    __syncthreads();
    #pragma unroll
    for (int o = 128; o > 0; o >>= 1) {
        if (tid < o) { sh_s[tid] += sh_s[tid + o]; sh_c[tid] += sh_c[tid + o]; }
        __syncthreads();
    }
    if (tid == 0) { g_bsum[blockIdx.x] = sh_s[0]; g_bcnt[blockIdx.x] = sh_c[0]; }
}

__global__ void final_kernel(float* __restrict__ out) {
    int lane = threadIdx.x;
    float s = g_bsum[lane], c = g_bcnt[lane];
    #pragma unroll
    for (int o = 16; o; o >>= 1) {
        s += __shfl_xor_sync(0xFFFFFFFFu, s, o);
        c += __shfl_xor_sync(0xFFFFFFFFu, c, o);
    }
    if (lane == 0) out[0] = (c > 0.0f) ? (s / c) : 0.0f;
}

extern "C" void kernel_launch(void* const* d_in, const int* in_sizes, int n_in,
                              void* d_out, int out_size) {
    const float* emb = (const float*)d_in[0];
    const int*   st  = (const int*)d_in[1];
    const int*   cn  = (const int*)d_in[2];
    float* out = (float*)d_out;

    cudaFuncSetAttribute(main_kernel, cudaFuncAttributeMaxDynamicSharedMemorySize,
                         SMEM_TOTAL);

    norm_kernel<<<BDIM / 8, dim3(32, 8)>>>(emb);
    main_kernel<<<(NT * (NT + 1)) / 2, 256, SMEM_TOTAL>>>(st, cn);
    combine_kernel<<<BDIM / 256, 256>>>();
    final_kernel<<<1, 32>>>(out);
}

// round 7
// speedup vs baseline: 7.9746x; 1.2708x over previous
#include <cuda_runtime.h>
#include <cuda_fp16.h>
#include <cstdint>

// B=8192, D=128. sim = (Z Z^T)/0.1 with masked logsumexps -> scalar mean.
// Single fp16 GEMM on mma.sync, K=128:
//   A = fp16(10*z), B = fp16(z); logit error ~8.6e-4 std -> final ~1e-5.
// Symmetry: upper-triangle tiles only; merged dual-anchor epilogue.
#define BDIM 8192
#define DDIM 128
#define TM   128
#define TN   128
#define KC   64
#define NSEG 128
#define NT   64
#define TTHRESH 365

__device__ __half g_za[BDIM * DDIM];          // 2MB: fp16(10*z)
__device__ __half g_zb[BDIM * DDIM];          // 2MB: fp16(z)
__device__ float2 g_part[BDIM * NSEG];        // 8MB
__device__ float  g_bsum[BDIM / 256];
__device__ float  g_bcnt[BDIM / 256];

// ---------------- PTX helpers (sm_80-portable only) ----------------
__device__ __forceinline__ uint32_t smem_u32(const void* p) {
    uint32_t a;
    asm("{ .reg .u64 t; cvta.to.shared.u64 t, %1; cvt.u32.u64 %0, t; }" : "=r"(a) : "l"(p));
    return a;
}
__device__ __forceinline__ void cp16(uint32_t dst, const void* src) {
    asm volatile("cp.async.cg.shared.global [%0], [%1], 16;" :: "r"(dst), "l"(src));
}
__device__ __forceinline__ void cp_commit() {
    asm volatile("cp.async.commit_group;" ::: "memory");
}
template <int N> __device__ __forceinline__ void cp_wait() {
    asm volatile("cp.async.wait_group %0;" :: "n"(N) : "memory");
}
__device__ __forceinline__ void ldsm4(uint32_t& r0, uint32_t& r1, uint32_t& r2,
                                      uint32_t& r3, uint32_t addr) {
    asm volatile("ldmatrix.sync.aligned.m8n8.x4.shared.b16 {%0,%1,%2,%3}, [%4];"
                 : "=r"(r0), "=r"(r1), "=r"(r2), "=r"(r3) : "r"(addr));
}
__device__ __forceinline__ void mma16816(float& d0, float& d1, float& d2, float& d3,
                                         uint32_t a0, uint32_t a1, uint32_t a2,
                                         uint32_t a3, uint32_t b0, uint32_t b1) {
    asm volatile(
        "mma.sync.aligned.m16n8k16.row.col.f32.f16.f16.f32 "
        "{%0,%1,%2,%3}, {%4,%5,%6,%7}, {%8,%9}, {%0,%1,%2,%3};"
        : "+f"(d0), "+f"(d1), "+f"(d2), "+f"(d3)
        : "r"(a0), "r"(a1), "r"(a2), "r"(a3), "r"(b0), "r"(b1));
}

// SMEM: 2 stages x (A 16K + B 16K) | colp 4K | ti/cenR/tj/cenC 4x512
#define SM_STAGE 32768
#define SM_COLP  65536
#define SM_TI    69632
#define SM_CENR  70144
#define SM_TJ    70656
#define SM_CENC  71168
#define SMEM_TOTAL 71680

// ---- Kernel 1: normalize + fp16 encode ----
__global__ void norm_kernel(const float* __restrict__ emb) {
    int row  = blockIdx.x * 8 + threadIdx.y;
    int lane = threadIdx.x;
    float4 v = ((const float4*)(emb + (size_t)row * DDIM))[lane];
    float ss = v.x * v.x + v.y * v.y + v.z * v.z + v.w * v.w;
    #pragma unroll
    for (int o = 16; o; o >>= 1) ss += __shfl_xor_sync(0xFFFFFFFFu, ss, o);
    float inv = rsqrtf(fmaxf(ss, 1e-24f));
    inv = inv * (1.5f - 0.5f * ss * inv * inv);
    float z[4] = {v.x * inv, v.y * inv, v.z * inv, v.w * inv};
    __half a[4], b[4];
    #pragma unroll
    for (int k = 0; k < 4; k++) {
        a[k] = __float2half_rn(z[k] * 10.0f);
        b[k] = __float2half_rn(z[k]);
    }
    size_t off = (size_t)row * DDIM + lane * 4;
    *(uint2*)(g_za + off) = *(uint2*)a;
    *(uint2*)(g_zb + off) = *(uint2*)b;
}

// ---- Kernel 2: upper-triangle tiles; fp16 GEMM + merged epilogue ----
__global__ void __launch_bounds__(256, 2)
main_kernel(const int* __restrict__ st, const int* __restrict__ cen) {
    extern __shared__ char smem[];
    const uint32_t sb = smem_u32(smem);
    const int tid   = threadIdx.x;
    const int wid   = tid >> 5;
    const int lane  = tid & 31;
    const int warpM = wid >> 1;
    const int warpN = wid & 1;

    // triangular decode
    const int t = blockIdx.x;
    int bx = (int)(64.5f - sqrtf(64.5f * 64.5f - 2.0f * (float)t));
    bx = bx < 0 ? 0 : (bx > 63 ? 63 : bx);
    #define FTRI(r) ((r) * NT - ((r) * ((r) - 1)) / 2)
    while (bx > 0 && FTRI(bx) > t) bx--;
    while (FTRI(bx + 1) <= t) bx++;
    const int by = bx + (t - FTRI(bx));
    const int rBase = bx * TM;
    const int cBase = by * TN;
    const bool isDiag = (bx == by);

    int* sTi   = (int*)(smem + SM_TI);
    int* sCenR = (int*)(smem + SM_CENR);
    int* sTj   = (int*)(smem + SM_TJ);
    int* sCenC = (int*)(smem + SM_CENC);
    if (tid < 128) {
        sTi[tid]   = st[rBase + tid];
        sCenR[tid] = cen[rBase + tid];
    } else {
        sTj[tid - 128]   = st[cBase + tid - 128];
        sCenC[tid - 128] = cen[cBase + tid - 128];
    }

    // Load both K-chunks (K=128 total) up front.
    #pragma unroll
    for (int c = 0; c < 2; c++) {
        uint32_t bA = sb + c * SM_STAGE;
        uint32_t bB = bA + 16384;
        #pragma unroll
        for (int u = 0; u < 4; u++) {
            int idx = u * 256 + tid;
            int row = idx >> 3, cc = idx & 7;
            uint32_t sw = (uint32_t)row * 128 + (uint32_t)((cc ^ (row & 7)) << 4);
            cp16(bA + sw, g_za + (size_t)(rBase + row) * DDIM + c * KC + cc * 8);
            cp16(bB + sw, g_zb + (size_t)(cBase + row) * DDIM + c * KC + cc * 8);
        }
    }
    cp_commit();

    float acc[2][8][4];
    #pragma unroll
    for (int mf = 0; mf < 2; mf++)
        #pragma unroll
        for (int nf = 0; nf < 8; nf++)
            #pragma unroll
            for (int r = 0; r < 4; r++) acc[mf][nf][r] = 0.0f;

    const int trow = lane & 7;
    const int tg1  = (lane >> 3) & 1;
    const int cadd = lane >> 4;
    const int rowA0 = warpM * 32 + tg1 * 8 + trow;
    const int rowB0 = warpN * 64 + tg1 * 8 + trow;

    cp_wait<0>();
    __syncthreads();

    #pragma unroll
    for (int c = 0; c < 2; c++) {
        uint32_t bA = sb + c * SM_STAGE;
        uint32_t bB = bA + 16384;
        #pragma unroll
        for (int kk = 0; kk < 4; kk++) {
            uint32_t aF[2][4], bF[4][4];
            #pragma unroll
            for (int mf = 0; mf < 2; mf++) {
                int row = rowA0 + mf * 16;
                uint32_t a = bA + row * 128 + (((kk * 2 + cadd) ^ (row & 7)) << 4);
                ldsm4(aF[mf][0], aF[mf][1], aF[mf][2], aF[mf][3], a);
            }
            #pragma unroll
            for (int np = 0; np < 4; np++) {
                int row = rowB0 + np * 16;
                uint32_t a = bB + row * 128 + (((kk * 2 + cadd) ^ (row & 7)) << 4);
                ldsm4(bF[np][0], bF[np][1], bF[np][2], bF[np][3], a);
            }
            #pragma unroll
            for (int mf = 0; mf < 2; mf++)
                #pragma unroll
                for (int np = 0; np < 4; np++) {
                    mma16816(acc[mf][np * 2][0], acc[mf][np * 2][1],
                             acc[mf][np * 2][2], acc[mf][np * 2][3],
                             aF[mf][0], aF[mf][1], aF[mf][2], aF[mf][3],
                             bF[np][0], bF[np][2]);
                    mma16816(acc[mf][np * 2 + 1][0], acc[mf][np * 2 + 1][1],
                             acc[mf][np * 2 + 1][2], acc[mf][np * 2 + 1][3],
                             aF[mf][0], aF[mf][1], aF[mf][2], aF[mf][3],
                             bF[np][1], bF[np][3]);
                }
        }
    }

    // ---------------- epilogue: acc = 10*sim -> e = exp ----------------
    #pragma unroll
    for (int mf = 0; mf < 2; mf++)
        #pragma unroll
        for (int nf = 0; nf < 8; nf++)
            #pragma unroll
            for (int r = 0; r < 4; r++) acc[mf][nf][r] = __expf(acc[mf][nf][r]);

    const int q  = lane >> 2;
    const int c2 = (lane & 3) * 2;

    int lrw[4], rti[4], rcn[4];
    float rsa[4], rsp[4];
    #pragma unroll
    for (int u = 0; u < 4; u++) {
        lrw[u] = warpM * 32 + (u >> 1) * 16 + (u & 1) * 8 + q;
        rti[u] = sTi[lrw[u]];
        rcn[u] = sCenR[lrw[u]];
        rsa[u] = 0.f;
        rsp[u] = 0.f;
    }

    // ---- merged row+col pass over all 64 fragment elements ----
    float2* colp = (float2*)(smem + SM_COLP);   // [4 warpM][128 cols]
    #pragma unroll
    for (int nf = 0; nf < 8; nf++) {
        const int lc0 = warpN * 64 + nf * 8 + c2;
        const int lc1 = lc0 + 1;
        const int tj0 = sTj[lc0], tj1 = sTj[lc1];
        const int cc0 = sCenC[lc0], cc1 = sCenC[lc1];
        float ca0 = 0.f, cp0 = 0.f, ca1 = 0.f, cp1 = 0.f;
        #pragma unroll
        for (int u = 0; u < 4; u++) {
            const int mf = u >> 1;
            const int rb = (u & 1) * 2;
            float e0 = acc[mf][nf][rb];
            float e1 = acc[mf][nf][rb + 1];
            int td0 = rti[u] - tj0; td0 = td0 < 0 ? -td0 : td0;
            int td1 = rti[u] - tj1; td1 = td1 < 0 ? -td1 : td1;
            bool in0 = td0 < TTHRESH, in1 = td1 < TTHRESH;
            bool self0 = isDiag && (lc0 == lrw[u]);
            bool self1 = isDiag && (lc1 == lrw[u]);
            if (!self0) {
                rsa[u] += e0;
                if (rcn[u] && in0) rsp[u] += e0;
                ca0 += e0;
                if (cc0 && in0) cp0 += e0;
            }
            if (!self1) {
                rsa[u] += e1;
                if (rcn[u] && in1) rsp[u] += e1;
                ca1 += e1;
                if (cc1 && in1) cp1 += e1;
            }
        }
        if (!isDiag) {
            #pragma unroll
            for (int o = 4; o <= 16; o <<= 1) {
                ca0 += __shfl_xor_sync(0xFFFFFFFFu, ca0, o);
                cp0 += __shfl_xor_sync(0xFFFFFFFFu, cp0, o);
                ca1 += __shfl_xor_sync(0xFFFFFFFFu, ca1, o);
                cp1 += __shfl_xor_sync(0xFFFFFFFFu, cp1, o);
            }
            if (q == 0) {
                colp[warpM * 128 + lc0] = make_float2(ca0, cp0);
                colp[warpM * 128 + lc1] = make_float2(ca1, cp1);
            }
        }
    }

    // ---- row-anchored writes ----
    #pragma unroll
    for (int u = 0; u < 4; u++) {
        float sa = rsa[u], sp = rsp[u];
        #pragma unroll
        for (int o = 1; o <= 2; o <<= 1) {
            sa += __shfl_xor_sync(0xFFFFFFFFu, sa, o);
            sp += __shfl_xor_sync(0xFFFFFFFFu, sp, o);
        }
        if ((lane & 3) == 0)
            g_part[(size_t)(rBase + lrw[u]) * NSEG + 2 * by + warpN] =
                make_float2(sa, sp);
    }

    // ---- col-anchored writes (off-diagonal only) ----
    if (!isDiag) {
        __syncthreads();
        const int mhalf = tid >> 7;
        const int col   = tid & 127;
        float2 v0 = colp[(2 * mhalf) * 128 + col];
        float2 v1 = colp[(2 * mhalf + 1) * 128 + col];
        g_part[(size_t)(cBase + col) * NSEG + 2 * bx + mhalf] =
            make_float2(v0.x + v1.x, v0.y + v1.y);
    }
}

// ---- Kernel 3: per-row merge + block partial reduction ----
__global__ void combine_kernel() {
    __shared__ float sh_s[256], sh_c[256];
    int tid = threadIdx.x;
    int row = blockIdx.x * 256 + tid;
    float sa = 0.0f, sp = 0.0f;
    const float4* p = (const float4*)(g_part + (size_t)row * NSEG);
    #pragma unroll
    for (int s = 0; s < NSEG / 2; s++) {
        float4 v = p[s];
        sa += v.x + v.z;
        sp += v.y + v.w;
    }
    float pr = 0.0f, c = 0.0f;
    if (sp > 0.0f) { pr = logf(sa) - logf(sp); c = 1.0f; }
    sh_s[tid] = pr; sh_c[tid] = c;
    __syncthreads();
    #pragma unroll
    for (int o = 128; o > 0; o >>= 1) {
        if (tid < o) { sh_s[tid] += sh_s[tid + o]; sh_c[tid] += sh_c[tid + o]; }
        __syncthreads();
    }
    if (tid == 0) { g_bsum[blockIdx.x] = sh_s[0]; g_bcnt[blockIdx.x] = sh_c[0]; }
}

__global__ void final_kernel(float* __restrict__ out) {
    int lane = threadIdx.x;
    float s = g_bsum[lane], c = g_bcnt[lane];
    #pragma unroll
    for (int o = 16; o; o >>= 1) {
        s += __shfl_xor_sync(0xFFFFFFFFu, s, o);
        c += __shfl_xor_sync(0xFFFFFFFFu, c, o);
    }
    if (lane == 0) out[0] = (c > 0.0f) ? (s / c) : 0.0f;
}

extern "C" void kernel_launch(void* const* d_in, const int* in_sizes, int n_in,
                              void* d_out, int out_size) {
    const float* emb = (const float*)d_in[0];
    const int*   st  = (const int*)d_in[1];
    const int*   cn  = (const int*)d_in[2];
    float* out = (float*)d_out;

    cudaFuncSetAttribute(main_kernel, cudaFuncAttributeMaxDynamicSharedMemorySize,
                         SMEM_TOTAL);

    norm_kernel<<<BDIM / 8, dim3(32, 8)>>>(emb);
    main_kernel<<<(NT * (NT + 1)) / 2, 256, SMEM_TOTAL>>>(st, cn);
    combine_kernel<<<BDIM / 256, 256>>>();
    final_kernel<<<1, 32>>>(out);
}

// round 8
// speedup vs baseline: 8.7614x; 1.0987x over previous
#include <cuda_runtime.h>
#include <cuda_fp16.h>
#include <cstdint>

// B=8192, D=128. sim = (Z Z^T)/0.1 with masked logsumexps -> scalar mean.
// Single fp16 GEMM on mma.sync, K=128, exp2-folded:
//   A = fp16(10*log2e * z), B = fp16(z); epilogue e = ex2(acc).
// Symmetry: upper-triangle tiles; merged dual-anchor packed-f32x2 epilogue.
#define BDIM 8192
#define DDIM 128
#define TM   128
#define TN   128
#define KC   64
#define NSEG 128
#define NT   64
#define TTHRESH 365

__device__ __half g_za[BDIM * DDIM];          // 2MB: fp16(14.427*z)
__device__ __half g_zb[BDIM * DDIM];          // 2MB: fp16(z)
__device__ float2 g_part[BDIM * NSEG];        // 8MB
__device__ float  g_bsum[BDIM / 256];
__device__ float  g_bcnt[BDIM / 256];
__device__ int    g_ticket = 0;

// ---------------- PTX helpers (sm_80-portable + f32x2 which sm_103 accepts) --
__device__ __forceinline__ uint32_t smem_u32(const void* p) {
    uint32_t a;
    asm("{ .reg .u64 t; cvta.to.shared.u64 t, %1; cvt.u32.u64 %0, t; }" : "=r"(a) : "l"(p));
    return a;
}
__device__ __forceinline__ void cp16(uint32_t dst, const void* src) {
    asm volatile("cp.async.cg.shared.global [%0], [%1], 16;" :: "r"(dst), "l"(src));
}
__device__ __forceinline__ void cp_commit() {
    asm volatile("cp.async.commit_group;" ::: "memory");
}
template <int N> __device__ __forceinline__ void cp_wait() {
    asm volatile("cp.async.wait_group %0;" :: "n"(N) : "memory");
}
__device__ __forceinline__ void ldsm4(uint32_t& r0, uint32_t& r1, uint32_t& r2,
                                      uint32_t& r3, uint32_t addr) {
    asm volatile("ldmatrix.sync.aligned.m8n8.x4.shared.b16 {%0,%1,%2,%3}, [%4];"
                 : "=r"(r0), "=r"(r1), "=r"(r2), "=r"(r3) : "r"(addr));
}
__device__ __forceinline__ void mma16816(float& d0, float& d1, float& d2, float& d3,
                                         uint32_t a0, uint32_t a1, uint32_t a2,
                                         uint32_t a3, uint32_t b0, uint32_t b1) {
    asm volatile(
        "mma.sync.aligned.m16n8k16.row.col.f32.f16.f16.f32 "
        "{%0,%1,%2,%3}, {%4,%5,%6,%7}, {%8,%9}, {%0,%1,%2,%3};"
        : "+f"(d0), "+f"(d1), "+f"(d2), "+f"(d3)
        : "r"(a0), "r"(a1), "r"(a2), "r"(a3), "r"(b0), "r"(b1));
}
__device__ __forceinline__ float ex2(float x) {
    float r;
    asm("ex2.approx.f32 %0, %1;" : "=f"(r) : "f"(x));
    return r;
}
__device__ __forceinline__ unsigned long long pk2(float lo, float hi) {
    unsigned long long r;
    asm("mov.b64 %0, {%1, %2};" : "=l"(r) : "f"(lo), "f"(hi));
    return r;
}
__device__ __forceinline__ void unpk2(unsigned long long v, float& lo, float& hi) {
    asm("mov.b64 {%0, %1}, %2;" : "=f"(lo), "=f"(hi) : "l"(v));
}
__device__ __forceinline__ unsigned long long add2(unsigned long long a,
                                                   unsigned long long b) {
    unsigned long long d;
    asm("add.rn.f32x2 %0, %1, %2;" : "=l"(d) : "l"(a), "l"(b));
    return d;
}

// SMEM: 2 K-chunks x (A 16K + B 16K) | colp 4K | ti/cenR/tj/cenC 4x512
#define SM_STAGE 32768
#define SM_COLP  65536
#define SM_TI    69632
#define SM_CENR  70144
#define SM_TJ    70656
#define SM_CENC  71168
#define SMEM_TOTAL 71680

// ---- Kernel 1: normalize + fp16 encode (exp2 scale folded into A) ----
__global__ void norm_kernel(const float* __restrict__ emb) {
    int row  = blockIdx.x * 8 + threadIdx.y;
    int lane = threadIdx.x;
    float4 v = ((const float4*)(emb + (size_t)row * DDIM))[lane];
    float ss = v.x * v.x + v.y * v.y + v.z * v.z + v.w * v.w;
    #pragma unroll
    for (int o = 16; o; o >>= 1) ss += __shfl_xor_sync(0xFFFFFFFFu, ss, o);
    float inv = rsqrtf(fmaxf(ss, 1e-24f));
    inv = inv * (1.5f - 0.5f * ss * inv * inv);
    const float SC = 14.426950408889634f;   // 10 / ln(2)
    float z[4] = {v.x * inv, v.y * inv, v.z * inv, v.w * inv};
    __half a[4], b[4];
    #pragma unroll
    for (int k = 0; k < 4; k++) {
        a[k] = __float2half_rn(z[k] * SC);
        b[k] = __float2half_rn(z[k]);
    }
    size_t off = (size_t)row * DDIM + lane * 4;
    *(uint2*)(g_za + off) = *(uint2*)a;
    *(uint2*)(g_zb + off) = *(uint2*)b;
}

// ---- Kernel 2: upper-triangle tiles; fp16 GEMM + packed epilogue ----
__global__ void __launch_bounds__(256, 2)
main_kernel(const int* __restrict__ st, const int* __restrict__ cen) {
    extern __shared__ char smem[];
    const uint32_t sb = smem_u32(smem);
    const int tid   = threadIdx.x;
    const int wid   = tid >> 5;
    const int lane  = tid & 31;
    const int warpM = wid >> 1;
    const int warpN = wid & 1;

    // triangular decode (incl. diagonal)
    const int t = blockIdx.x;
    int bx = (int)(64.5f - sqrtf(64.5f * 64.5f - 2.0f * (float)t));
    bx = bx < 0 ? 0 : (bx > 63 ? 63 : bx);
    #define FTRI(r) ((r) * NT - ((r) * ((r) - 1)) / 2)
    while (bx > 0 && FTRI(bx) > t) bx--;
    while (FTRI(bx + 1) <= t) bx++;
    const int by = bx + (t - FTRI(bx));
    const int rBase = bx * TM;
    const int cBase = by * TN;
    const bool isDiag = (bx == by);

    int* sTi   = (int*)(smem + SM_TI);
    int* sCenR = (int*)(smem + SM_CENR);
    int* sTj   = (int*)(smem + SM_TJ);
    int* sCenC = (int*)(smem + SM_CENC);
    if (tid < 128) {
        sTi[tid]   = st[rBase + tid];
        sCenR[tid] = cen[rBase + tid];
    } else {
        sTj[tid - 128]   = st[cBase + tid - 128];
        sCenC[tid - 128] = cen[cBase + tid - 128];
    }

    // Load both K-chunks (K=128) up front.
    #pragma unroll
    for (int c = 0; c < 2; c++) {
        uint32_t bA = sb + c * SM_STAGE;
        uint32_t bB = bA + 16384;
        #pragma unroll
        for (int u = 0; u < 4; u++) {
            int idx = u * 256 + tid;
            int row = idx >> 3, cc = idx & 7;
            uint32_t sw = (uint32_t)row * 128 + (uint32_t)((cc ^ (row & 7)) << 4);
            cp16(bA + sw, g_za + (size_t)(rBase + row) * DDIM + c * KC + cc * 8);
            cp16(bB + sw, g_zb + (size_t)(cBase + row) * DDIM + c * KC + cc * 8);
        }
    }
    cp_commit();

    float acc[2][8][4];
    #pragma unroll
    for (int mf = 0; mf < 2; mf++)
        #pragma unroll
        for (int nf = 0; nf < 8; nf++)
            #pragma unroll
            for (int r = 0; r < 4; r++) acc[mf][nf][r] = 0.0f;

    const int trow = lane & 7;
    const int tg1  = (lane >> 3) & 1;
    const int cadd = lane >> 4;
    const int rowA0 = warpM * 32 + tg1 * 8 + trow;
    const int rowB0 = warpN * 64 + tg1 * 8 + trow;

    cp_wait<0>();
    __syncthreads();

    #pragma unroll
    for (int c = 0; c < 2; c++) {
        uint32_t bA = sb + c * SM_STAGE;
        uint32_t bB = bA + 16384;
        #pragma unroll
        for (int kk = 0; kk < 4; kk++) {
            uint32_t aF[2][4], bF[4][4];
            #pragma unroll
            for (int mf = 0; mf < 2; mf++) {
                int row = rowA0 + mf * 16;
                uint32_t a = bA + row * 128 + (((kk * 2 + cadd) ^ (row & 7)) << 4);
                ldsm4(aF[mf][0], aF[mf][1], aF[mf][2], aF[mf][3], a);
            }
            #pragma unroll
            for (int np = 0; np < 4; np++) {
                int row = rowB0 + np * 16;
                uint32_t a = bB + row * 128 + (((kk * 2 + cadd) ^ (row & 7)) << 4);
                ldsm4(bF[np][0], bF[np][1], bF[np][2], bF[np][3], a);
            }
            #pragma unroll
            for (int mf = 0; mf < 2; mf++)
                #pragma unroll
                for (int np = 0; np < 4; np++) {
                    mma16816(acc[mf][np * 2][0], acc[mf][np * 2][1],
                             acc[mf][np * 2][2], acc[mf][np * 2][3],
                             aF[mf][0], aF[mf][1], aF[mf][2], aF[mf][3],
                             bF[np][0], bF[np][2]);
                    mma16816(acc[mf][np * 2 + 1][0], acc[mf][np * 2 + 1][1],
                             acc[mf][np * 2 + 1][2], acc[mf][np * 2 + 1][3],
                             aF[mf][0], aF[mf][1], aF[mf][2], aF[mf][3],
                             bF[np][1], bF[np][3]);
                }
        }
    }

    // -------- epilogue: acc = log2-domain logits -> e = 2^acc --------
    #pragma unroll
    for (int mf = 0; mf < 2; mf++)
        #pragma unroll
        for (int nf = 0; nf < 8; nf++)
            #pragma unroll
            for (int r = 0; r < 4; r++) acc[mf][nf][r] = ex2(acc[mf][nf][r]);

    const int q  = lane >> 2;
    const int c2 = (lane & 3) * 2;

    int lrw[4], rti[4], rcn[4];
    unsigned long long prs[4];   // packed (sum_all, sum_inwindow) per row slot
    #pragma unroll
    for (int u = 0; u < 4; u++) {
        lrw[u] = warpM * 32 + (u >> 1) * 16 + (u & 1) * 8 + q;
        rti[u] = sTi[lrw[u]];
        rcn[u] = sCenR[lrw[u]];
        prs[u] = 0ull;
    }

    float2* colp = (float2*)(smem + SM_COLP);   // [4 warpM][128 cols]

    if (!isDiag) {
        // fast path: no self mask; row + col packed accumulation
        #pragma unroll
        for (int nf = 0; nf < 8; nf++) {
            const int lc0 = warpN * 64 + nf * 8 + c2;
            const int lc1 = lc0 + 1;
            const int tj0 = sTj[lc0], tj1 = sTj[lc1];
            unsigned long long pca0 = 0ull, pca1 = 0ull;
            #pragma unroll
            for (int u = 0; u < 4; u++) {
                const int mf = u >> 1;
                const int rb = (u & 1) * 2;
                float e0 = acc[mf][nf][rb];
                float e1 = acc[mf][nf][rb + 1];
                bool in0 = (unsigned)(rti[u] - tj0 + 364) <= 728u;
                bool in1 = (unsigned)(rti[u] - tj1 + 364) <= 728u;
                unsigned long long pk0 = pk2(e0, in0 ? e0 : 0.0f);
                unsigned long long pk1 = pk2(e1, in1 ? e1 : 0.0f);
                prs[u] = add2(prs[u], pk0);
                prs[u] = add2(prs[u], pk1);
                pca0 = add2(pca0, pk0);
                pca1 = add2(pca1, pk1);
            }
            float ca0, cw0, ca1, cw1;
            unpk2(pca0, ca0, cw0);
            unpk2(pca1, ca1, cw1);
            #pragma unroll
            for (int o = 4; o <= 16; o <<= 1) {
                ca0 += __shfl_xor_sync(0xFFFFFFFFu, ca0, o);
                cw0 += __shfl_xor_sync(0xFFFFFFFFu, cw0, o);
                ca1 += __shfl_xor_sync(0xFFFFFFFFu, ca1, o);
                cw1 += __shfl_xor_sync(0xFFFFFFFFu, cw1, o);
            }
            if (q == 0) {
                colp[warpM * 128 + lc0] =
                    make_float2(ca0, sCenC[lc0] ? cw0 : 0.0f);
                colp[warpM * 128 + lc1] =
                    make_float2(ca1, sCenC[lc1] ? cw1 : 0.0f);
            }
        }
    } else {
        // diagonal tile: self exclusion, row sums only
        #pragma unroll
        for (int nf = 0; nf < 8; nf++) {
            const int lc0 = warpN * 64 + nf * 8 + c2;
            const int lc1 = lc0 + 1;
            const int tj0 = sTj[lc0], tj1 = sTj[lc1];
            #pragma unroll
            for (int u = 0; u < 4; u++) {
                const int mf = u >> 1;
                const int rb = (u & 1) * 2;
                float e0 = acc[mf][nf][rb];
                float e1 = acc[mf][nf][rb + 1];
                bool in0 = (unsigned)(rti[u] - tj0 + 364) <= 728u;
                bool in1 = (unsigned)(rti[u] - tj1 + 364) <= 728u;
                if (lc0 != lrw[u]) prs[u] = add2(prs[u], pk2(e0, in0 ? e0 : 0.0f));
                if (lc1 != lrw[u]) prs[u] = add2(prs[u], pk2(e1, in1 ? e1 : 0.0f));
            }
        }
    }

    // ---- row-anchored writes (censor applied post-loop) ----
    #pragma unroll
    for (int u = 0; u < 4; u++) {
        float sa, sw;
        unpk2(prs[u], sa, sw);
        float sp = rcn[u] ? sw : 0.0f;
        #pragma unroll
        for (int o = 1; o <= 2; o <<= 1) {
            sa += __shfl_xor_sync(0xFFFFFFFFu, sa, o);
            sp += __shfl_xor_sync(0xFFFFFFFFu, sp, o);
        }
        if ((lane & 3) == 0)
            g_part[(size_t)(rBase + lrw[u]) * NSEG + 2 * by + warpN] =
                make_float2(sa, sp);
    }

    // ---- col-anchored writes (off-diagonal only) ----
    if (!isDiag) {
        __syncthreads();
        const int mhalf = tid >> 7;
        const int col   = tid & 127;
        float2 v0 = colp[(2 * mhalf) * 128 + col];
        float2 v1 = colp[(2 * mhalf + 1) * 128 + col];
        g_part[(size_t)(cBase + col) * NSEG + 2 * bx + mhalf] =
            make_float2(v0.x + v1.x, v0.y + v1.y);
    }
}

// ---- Kernel 3: per-row merge + block reduce + last-block final reduce ----
__global__ void combine_kernel(float* __restrict__ out) {
    __shared__ float sh_s[256], sh_c[256];
    __shared__ int s_last;
    int tid = threadIdx.x;
    int row = blockIdx.x * 256 + tid;
    float sa = 0.0f, sp = 0.0f;
    const float4* p = (const float4*)(g_part + (size_t)row * NSEG);
    #pragma unroll
    for (int s = 0; s < NSEG / 2; s++) {
        float4 v = p[s];
        sa += v.x + v.z;
        sp += v.y + v.w;
    }
    float pr = 0.0f, c = 0.0f;
    if (sp > 0.0f) { pr = __logf(sa) - __logf(sp); c = 1.0f; }
    sh_s[tid] = pr; sh_c[tid] = c;
    __syncthreads();
    #pragma unroll
    for (int o = 128; o > 0; o >>= 1) {
        if (tid < o) { sh_s[tid] += sh_s[tid + o]; sh_c[tid] += sh_c[tid + o]; }
        __syncthreads();
    }
    if (tid == 0) {
        g_bsum[blockIdx.x] = sh_s[0];
        g_bcnt[blockIdx.x] = sh_c[0];
        __threadfence();
        int tk = atomicAdd(&g_ticket, 1);
        s_last = (tk == (int)gridDim.x - 1);
    }
    __syncthreads();
    if (s_last && tid < 32) {
        float s = g_bsum[tid], cc = g_bcnt[tid];   // gridDim.x == 32
        #pragma unroll
        for (int o = 16; o; o >>= 1) {
            s  += __shfl_xor_sync(0xFFFFFFFFu, s, o);
            cc += __shfl_xor_sync(0xFFFFFFFFu, cc, o);
        }
        if (tid == 0) {
            out[0] = (cc > 0.0f) ? (s / cc) : 0.0f;
            g_ticket = 0;   // reset for graph replay
        }
    }
}

extern "C" void kernel_launch(void* const* d_in, const int* in_sizes, int n_in,
                              void* d_out, int out_size) {
    const float* emb = (const float*)d_in[0];
    const int*   st  = (const int*)d_in[1];
    const int*   cn  = (const int*)d_in[2];
    float* out = (float*)d_out;

    cudaFuncSetAttribute(main_kernel, cudaFuncAttributeMaxDynamicSharedMemorySize,
                         SMEM_TOTAL);

    norm_kernel<<<BDIM / 8, dim3(32, 8)>>>(emb);
    main_kernel<<<(NT * (NT + 1)) / 2, 256, SMEM_TOTAL>>>(st, cn);
    combine_kernel<<<BDIM / 256, 256>>>(out);
}

// round 9
// speedup vs baseline: 9.3816x; 1.0708x over previous
#include <cuda_runtime.h>
#include <cuda_fp16.h>
#include <cstdint>

// B=8192, D=128. sim = (Z Z^T)/0.1 with masked logsumexps -> scalar mean.
// fp16 GEMM with *fp16 accumulation* on mma.sync, K=128, exp2-folded:
//   A = fp16(10*log2e * z), B = fp16(z); epilogue e = ex2(cvt_f32(acc)).
// Symmetry: upper-triangle tiles; merged dual-anchor packed-f32x2 epilogue.
#define BDIM 8192
#define DDIM 128
#define TM   128
#define TN   128
#define KC   64
#define NSEG 128
#define NT   64
#define TTHRESH 365

__device__ __half g_za[BDIM * DDIM];          // 2MB: fp16(14.427*z)
__device__ __half g_zb[BDIM * DDIM];          // 2MB: fp16(z)
__device__ float2 g_part[BDIM * NSEG];        // 8MB
__device__ float  g_bsum[BDIM / 256];
__device__ float  g_bcnt[BDIM / 256];
__device__ int    g_ticket = 0;

// ---------------- PTX helpers ----------------
__device__ __forceinline__ uint32_t smem_u32(const void* p) {
    uint32_t a;
    asm("{ .reg .u64 t; cvta.to.shared.u64 t, %1; cvt.u32.u64 %0, t; }" : "=r"(a) : "l"(p));
    return a;
}
__device__ __forceinline__ void cp16(uint32_t dst, const void* src) {
    asm volatile("cp.async.cg.shared.global [%0], [%1], 16;" :: "r"(dst), "l"(src));
}
__device__ __forceinline__ void cp_commit() {
    asm volatile("cp.async.commit_group;" ::: "memory");
}
template <int N> __device__ __forceinline__ void cp_wait() {
    asm volatile("cp.async.wait_group %0;" :: "n"(N) : "memory");
}
__device__ __forceinline__ void ldsm4(uint32_t& r0, uint32_t& r1, uint32_t& r2,
                                      uint32_t& r3, uint32_t addr) {
    asm volatile("ldmatrix.sync.aligned.m8n8.x4.shared.b16 {%0,%1,%2,%3}, [%4];"
                 : "=r"(r0), "=r"(r1), "=r"(r2), "=r"(r3) : "r"(addr));
}
// f16-accumulate HMMA: D,C are 2 b32 regs (4 f16). Reg k packs cols (c,c+1)
// of row-group k (rows q and q+8), matching the f32 layout d[2k],d[2k+1].
__device__ __forceinline__ void mma16816h(uint32_t& d0, uint32_t& d1,
                                          uint32_t a0, uint32_t a1, uint32_t a2,
                                          uint32_t a3, uint32_t b0, uint32_t b1) {
    asm volatile(
        "mma.sync.aligned.m16n8k16.row.col.f16.f16.f16.f16 "
        "{%0,%1}, {%2,%3,%4,%5}, {%6,%7}, {%0,%1};"
        : "+r"(d0), "+r"(d1)
        : "r"(a0), "r"(a1), "r"(a2), "r"(a3), "r"(b0), "r"(b1));
}
__device__ __forceinline__ float ex2(float x) {
    float r;
    asm("ex2.approx.f32 %0, %1;" : "=f"(r) : "f"(x));
    return r;
}
__device__ __forceinline__ unsigned long long pk2(float lo, float hi) {
    unsigned long long r;
    asm("mov.b64 %0, {%1, %2};" : "=l"(r) : "f"(lo), "f"(hi));
    return r;
}
__device__ __forceinline__ void unpk2(unsigned long long v, float& lo, float& hi) {
    asm("mov.b64 {%0, %1}, %2;" : "=f"(lo), "=f"(hi) : "l"(v));
}
__device__ __forceinline__ unsigned long long add2(unsigned long long a,
                                                   unsigned long long b) {
    unsigned long long d;
    asm("add.rn.f32x2 %0, %1, %2;" : "=l"(d) : "l"(a), "l"(b));
    return d;
}

// SMEM: 2 K-chunks x (A 16K + B 16K) | colp 4K | ti/cenR/tj/cenC 4x512
#define SM_STAGE 32768
#define SM_COLP  65536
#define SM_TI    69632
#define SM_CENR  70144
#define SM_TJ    70656
#define SM_CENC  71168
#define SMEM_TOTAL 71680

// ---- Kernel 1: normalize + fp16 encode (exp2 scale folded into A) ----
__global__ void norm_kernel(const float* __restrict__ emb) {
    int row  = blockIdx.x * 8 + threadIdx.y;
    int lane = threadIdx.x;
    float4 v = ((const float4*)(emb + (size_t)row * DDIM))[lane];
    float ss = v.x * v.x + v.y * v.y + v.z * v.z + v.w * v.w;
    #pragma unroll
    for (int o = 16; o; o >>= 1) ss += __shfl_xor_sync(0xFFFFFFFFu, ss, o);
    float inv = rsqrtf(fmaxf(ss, 1e-24f));
    inv = inv * (1.5f - 0.5f * ss * inv * inv);
    const float SC = 14.426950408889634f;   // 10 / ln(2)
    float z[4] = {v.x * inv, v.y * inv, v.z * inv, v.w * inv};
    __half a[4], b[4];
    #pragma unroll
    for (int k = 0; k < 4; k++) {
        a[k] = __float2half_rn(z[k] * SC);
        b[k] = __float2half_rn(z[k]);
    }
    size_t off = (size_t)row * DDIM + lane * 4;
    *(uint2*)(g_za + off) = *(uint2*)a;
    *(uint2*)(g_zb + off) = *(uint2*)b;
}

// ---- Kernel 2: upper-triangle tiles; fp16-acc GEMM + packed epilogue ----
__global__ void __launch_bounds__(256, 2)
main_kernel(const int* __restrict__ st, const int* __restrict__ cen) {
    extern __shared__ char smem[];
    const uint32_t sb = smem_u32(smem);
    const int tid   = threadIdx.x;
    const int wid   = tid >> 5;
    const int lane  = tid & 31;
    const int warpM = wid >> 1;
    const int warpN = wid & 1;

    // triangular decode
    const int t = blockIdx.x;
    int bx = (int)(64.5f - sqrtf(64.5f * 64.5f - 2.0f * (float)t));
    bx = bx < 0 ? 0 : (bx > 63 ? 63 : bx);
    #define FTRI(r) ((r) * NT - ((r) * ((r) - 1)) / 2)
    while (bx > 0 && FTRI(bx) > t) bx--;
    while (FTRI(bx + 1) <= t) bx++;
    const int by = bx + (t - FTRI(bx));
    const int rBase = bx * TM;
    const int cBase = by * TN;
    const bool isDiag = (bx == by);

    int* sTi   = (int*)(smem + SM_TI);
    int* sCenR = (int*)(smem + SM_CENR);
    int* sTj   = (int*)(smem + SM_TJ);
    int* sCenC = (int*)(smem + SM_CENC);
    if (tid < 128) {
        sTi[tid]   = st[rBase + tid];
        sCenR[tid] = cen[rBase + tid];
    } else {
        sTj[tid - 128]   = st[cBase + tid - 128];
        sCenC[tid - 128] = cen[cBase + tid - 128];
    }

    // Load both K-chunks (K=128) up front.
    #pragma unroll
    for (int c = 0; c < 2; c++) {
        uint32_t bA = sb + c * SM_STAGE;
        uint32_t bB = bA + 16384;
        #pragma unroll
        for (int u = 0; u < 4; u++) {
            int idx = u * 256 + tid;
            int row = idx >> 3, cc = idx & 7;
            uint32_t sw = (uint32_t)row * 128 + (uint32_t)((cc ^ (row & 7)) << 4);
            cp16(bA + sw, g_za + (size_t)(rBase + row) * DDIM + c * KC + cc * 8);
            cp16(bB + sw, g_zb + (size_t)(cBase + row) * DDIM + c * KC + cc * 8);
        }
    }
    cp_commit();

    // fp16 accumulators: acc[mf][nf][rg] packs cols (c2, c2+1) of row-group rg
    uint32_t acc[2][8][2];
    #pragma unroll
    for (int mf = 0; mf < 2; mf++)
        #pragma unroll
        for (int nf = 0; nf < 8; nf++) {
            acc[mf][nf][0] = 0u;
            acc[mf][nf][1] = 0u;
        }

    const int trow = lane & 7;
    const int tg1  = (lane >> 3) & 1;
    const int cadd = lane >> 4;
    const int rowA0 = warpM * 32 + tg1 * 8 + trow;
    const int rowB0 = warpN * 64 + tg1 * 8 + trow;

    cp_wait<0>();
    __syncthreads();

    #pragma unroll
    for (int c = 0; c < 2; c++) {
        uint32_t bA = sb + c * SM_STAGE;
        uint32_t bB = bA + 16384;
        #pragma unroll
        for (int kk = 0; kk < 4; kk++) {
            uint32_t aF[2][4], bF[4][4];
            #pragma unroll
            for (int mf = 0; mf < 2; mf++) {
                int row = rowA0 + mf * 16;
                uint32_t a = bA + row * 128 + (((kk * 2 + cadd) ^ (row & 7)) << 4);
                ldsm4(aF[mf][0], aF[mf][1], aF[mf][2], aF[mf][3], a);
            }
            #pragma unroll
            for (int np = 0; np < 4; np++) {
                int row = rowB0 + np * 16;
                uint32_t a = bB + row * 128 + (((kk * 2 + cadd) ^ (row & 7)) << 4);
                ldsm4(bF[np][0], bF[np][1], bF[np][2], bF[np][3], a);
            }
            #pragma unroll
            for (int mf = 0; mf < 2; mf++)
                #pragma unroll
                for (int np = 0; np < 4; np++) {
                    mma16816h(acc[mf][np * 2][0], acc[mf][np * 2][1],
                              aF[mf][0], aF[mf][1], aF[mf][2], aF[mf][3],
                              bF[np][0], bF[np][2]);
                    mma16816h(acc[mf][np * 2 + 1][0], acc[mf][np * 2 + 1][1],
                              aF[mf][0], aF[mf][1], aF[mf][2], aF[mf][3],
                              bF[np][1], bF[np][3]);
                }
        }
    }

    // -------- epilogue: acc = fp16 log2-domain logits --------
    const int q  = lane >> 2;
    const int c2 = (lane & 3) * 2;

    int lrw[4], rti[4], rcn[4];
    unsigned long long prs[4];   // packed (sum_all, sum_inwindow) per row slot
    #pragma unroll
    for (int u = 0; u < 4; u++) {
        lrw[u] = warpM * 32 + (u >> 1) * 16 + (u & 1) * 8 + q;
        rti[u] = sTi[lrw[u]];
        rcn[u] = sCenR[lrw[u]];
        prs[u] = 0ull;
    }

    float2* colp = (float2*)(smem + SM_COLP);   // [4 warpM][128 cols]

    if (!isDiag) {
        #pragma unroll
        for (int nf = 0; nf < 8; nf++) {
            const int lc0 = warpN * 64 + nf * 8 + c2;
            const int lc1 = lc0 + 1;
            const int tj0 = sTj[lc0], tj1 = sTj[lc1];
            unsigned long long pca0 = 0ull, pca1 = 0ull;
            #pragma unroll
            for (int u = 0; u < 4; u++) {
                const int mf = u >> 1;
                const int rg = u & 1;
                float2 f = __half22float2(
                    *reinterpret_cast<__half2*>(&acc[mf][nf][rg]));
                float e0 = ex2(f.x);
                float e1 = ex2(f.y);
                bool in0 = (unsigned)(rti[u] - tj0 + 364) <= 728u;
                bool in1 = (unsigned)(rti[u] - tj1 + 364) <= 728u;
                unsigned long long pk0 = pk2(e0, in0 ? e0 : 0.0f);
                unsigned long long pk1 = pk2(e1, in1 ? e1 : 0.0f);
                prs[u] = add2(prs[u], pk0);
                prs[u] = add2(prs[u], pk1);
                pca0 = add2(pca0, pk0);
                pca1 = add2(pca1, pk1);
            }
            float ca0, cw0, ca1, cw1;
            unpk2(pca0, ca0, cw0);
            unpk2(pca1, ca1, cw1);
            #pragma unroll
            for (int o = 4; o <= 16; o <<= 1) {
                ca0 += __shfl_xor_sync(0xFFFFFFFFu, ca0, o);
                cw0 += __shfl_xor_sync(0xFFFFFFFFu, cw0, o);
                ca1 += __shfl_xor_sync(0xFFFFFFFFu, ca1, o);
                cw1 += __shfl_xor_sync(0xFFFFFFFFu, cw1, o);
            }
            if (q == 0) {
                colp[warpM * 128 + lc0] =
                    make_float2(ca0, sCenC[lc0] ? cw0 : 0.0f);
                colp[warpM * 128 + lc1] =
                    make_float2(ca1, sCenC[lc1] ? cw1 : 0.0f);
            }
        }
    } else {
        #pragma unroll
        for (int nf = 0; nf < 8; nf++) {
            const int lc0 = warpN * 64 + nf * 8 + c2;
            const int lc1 = lc0 + 1;
            const int tj0 = sTj[lc0], tj1 = sTj[lc1];
            #pragma unroll
            for (int u = 0; u < 4; u++) {
                const int mf = u >> 1;
                const int rg = u & 1;
                float2 f = __half22float2(
                    *reinterpret_cast<__half2*>(&acc[mf][nf][rg]));
                float e0 = ex2(f.x);
                float e1 = ex2(f.y);
                bool in0 = (unsigned)(rti[u] - tj0 + 364) <= 728u;
                bool in1 = (unsigned)(rti[u] - tj1 + 364) <= 728u;
                if (lc0 != lrw[u]) prs[u] = add2(prs[u], pk2(e0, in0 ? e0 : 0.0f));
                if (lc1 != lrw[u]) prs[u] = add2(prs[u], pk2(e1, in1 ? e1 : 0.0f));
            }
        }
    }

    // ---- row-anchored writes (censor applied post-loop) ----
    #pragma unroll
    for (int u = 0; u < 4; u++) {
        float sa, sw;
        unpk2(prs[u], sa, sw);
        float sp = rcn[u] ? sw : 0.0f;
        #pragma unroll
        for (int o = 1; o <= 2; o <<= 1) {
            sa += __shfl_xor_sync(0xFFFFFFFFu, sa, o);
            sp += __shfl_xor_sync(0xFFFFFFFFu, sp, o);
        }
        if ((lane & 3) == 0)
            g_part[(size_t)(rBase + lrw[u]) * NSEG + 2 * by + warpN] =
                make_float2(sa, sp);
    }

    // ---- col-anchored writes (off-diagonal only) ----
    if (!isDiag) {
        __syncthreads();
        const int mhalf = tid >> 7;
        const int col   = tid & 127;
        float2 v0 = colp[(2 * mhalf) * 128 + col];
        float2 v1 = colp[(2 * mhalf + 1) * 128 + col];
        g_part[(size_t)(cBase + col) * NSEG + 2 * bx + mhalf] =
            make_float2(v0.x + v1.x, v0.y + v1.y);
    }
}

// ---- Kernel 3: per-row merge + block reduce + last-block final reduce ----
__global__ void combine_kernel(float* __restrict__ out) {
    __shared__ float sh_s[256], sh_c[256];
    __shared__ int s_last;
    int tid = threadIdx.x;
    int row = blockIdx.x * 256 + tid;
    float sa = 0.0f, sp = 0.0f;
    const float4* p = (const float4*)(g_part + (size_t)row * NSEG);
    #pragma unroll
    for (int s = 0; s < NSEG / 2; s++) {
        float4 v = p[s];
        sa += v.x + v.z;
        sp += v.y + v.w;
    }
    float pr = 0.0f, c = 0.0f;
    if (sp > 0.0f) { pr = __logf(sa) - __logf(sp); c = 1.0f; }
    sh_s[tid] = pr; sh_c[tid] = c;
    __syncthreads();
    #pragma unroll
    for (int o = 128; o > 0; o >>= 1) {
        if (tid < o) { sh_s[tid] += sh_s[tid + o]; sh_c[tid] += sh_c[tid + o]; }
        __syncthreads();
    }
    if (tid == 0) {
        g_bsum[blockIdx.x] = sh_s[0];
        g_bcnt[blockIdx.x] = sh_c[0];
        __threadfence();
        int tk = atomicAdd(&g_ticket, 1);
        s_last = (tk == (int)gridDim.x - 1);
    }
    __syncthreads();
    if (s_last && tid < 32) {
        float s = g_bsum[tid], cc = g_bcnt[tid];   // gridDim.x == 32
        #pragma unroll
        for (int o = 16; o; o >>= 1) {
            s  += __shfl_xor_sync(0xFFFFFFFFu, s, o);
            cc += __shfl_xor_sync(0xFFFFFFFFu, cc, o);
        }
        if (tid == 0) {
            out[0] = (cc > 0.0f) ? (s / cc) : 0.0f;
            g_ticket = 0;   // reset for graph replay
        }
    }
}

extern "C" void kernel_launch(void* const* d_in, const int* in_sizes, int n_in,
                              void* d_out, int out_size) {
    const float* emb = (const float*)d_in[0];
    const int*   st  = (const int*)d_in[1];
    const int*   cn  = (const int*)d_in[2];
    float* out = (float*)d_out;

    cudaFuncSetAttribute(main_kernel, cudaFuncAttributeMaxDynamicSharedMemorySize,
                         SMEM_TOTAL);

    norm_kernel<<<BDIM / 8, dim3(32, 8)>>>(emb);
    main_kernel<<<(NT * (NT + 1)) / 2, 256, SMEM_TOTAL>>>(st, cn);
    combine_kernel<<<BDIM / 256, 256>>>(out);
}

// round 10
// speedup vs baseline: 9.4548x; 1.0078x over previous
#include <cuda_runtime.h>
#include <cuda_fp16.h>
#include <cstdint>

// B=8192, D=128. sim = (Z Z^T)/0.1 with masked logsumexps -> scalar mean.
// fp16 GEMM with fp16 accumulation on mma.sync, K=128, exp2-folded:
//   A = fp16(10*log2e * z), B = fp16(z); epilogue e = ex2.f16x2(acc).
// Upper-triangle tiles; merged dual-anchor packed-f32x2 epilogue.
// This round: 2-group cp.async pipelining + packed fp16x2 ex2.
#define BDIM 8192
#define DDIM 128
#define TM   128
#define TN   128
#define KC   64
#define NSEG 128
#define NT   64
#define TTHRESH 365

__device__ __half g_za[BDIM * DDIM];          // 2MB: fp16(14.427*z)
__device__ __half g_zb[BDIM * DDIM];          // 2MB: fp16(z)
__device__ float2 g_part[BDIM * NSEG];        // 8MB
__device__ float  g_bsum[BDIM / 256];
__device__ float  g_bcnt[BDIM / 256];
__device__ int    g_ticket = 0;

// ---------------- PTX helpers ----------------
__device__ __forceinline__ uint32_t smem_u32(const void* p) {
    uint32_t a;
    asm("{ .reg .u64 t; cvta.to.shared.u64 t, %1; cvt.u32.u64 %0, t; }" : "=r"(a) : "l"(p));
    return a;
}
__device__ __forceinline__ void cp16(uint32_t dst, const void* src) {
    asm volatile("cp.async.cg.shared.global [%0], [%1], 16;" :: "r"(dst), "l"(src));
}
__device__ __forceinline__ void cp_commit() {
    asm volatile("cp.async.commit_group;" ::: "memory");
}
template <int N> __device__ __forceinline__ void cp_wait() {
    asm volatile("cp.async.wait_group %0;" :: "n"(N) : "memory");
}
__device__ __forceinline__ void ldsm4(uint32_t& r0, uint32_t& r1, uint32_t& r2,
                                      uint32_t& r3, uint32_t addr) {
    asm volatile("ldmatrix.sync.aligned.m8n8.x4.shared.b16 {%0,%1,%2,%3}, [%4];"
                 : "=r"(r0), "=r"(r1), "=r"(r2), "=r"(r3) : "r"(addr));
}
// f16-accumulate HMMA: D,C are 2 b32 regs (4 f16).
__device__ __forceinline__ void mma16816h(uint32_t& d0, uint32_t& d1,
                                          uint32_t a0, uint32_t a1, uint32_t a2,
                                          uint32_t a3, uint32_t b0, uint32_t b1) {
    asm volatile(
        "mma.sync.aligned.m16n8k16.row.col.f16.f16.f16.f16 "
        "{%0,%1}, {%2,%3,%4,%5}, {%6,%7}, {%0,%1};"
        : "+r"(d0), "+r"(d1)
        : "r"(a0), "r"(a1), "r"(a2), "r"(a3), "r"(b0), "r"(b1));
}
__device__ __forceinline__ uint32_t ex2h2(uint32_t x) {
    uint32_t r;
    asm("ex2.approx.f16x2 %0, %1;" : "=r"(r) : "r"(x));
    return r;
}
__device__ __forceinline__ unsigned long long pk2(float lo, float hi) {
    unsigned long long r;
    asm("mov.b64 %0, {%1, %2};" : "=l"(r) : "f"(lo), "f"(hi));
    return r;
}
__device__ __forceinline__ void unpk2(unsigned long long v, float& lo, float& hi) {
    asm("mov.b64 {%0, %1}, %2;" : "=f"(lo), "=f"(hi) : "l"(v));
}
__device__ __forceinline__ unsigned long long add2(unsigned long long a,
                                                   unsigned long long b) {
    unsigned long long d;
    asm("add.rn.f32x2 %0, %1, %2;" : "=l"(d) : "l"(a), "l"(b));
    return d;
}

// SMEM: 2 K-chunks x (A 16K + B 16K) | colp 4K | ti/cenR/tj/cenC 4x512
#define SM_STAGE 32768
#define SM_COLP  65536
#define SM_TI    69632
#define SM_CENR  70144
#define SM_TJ    70656
#define SM_CENC  71168
#define SMEM_TOTAL 71680

// ---- Kernel 1: normalize + fp16 encode (exp2 scale folded into A) ----
__global__ void norm_kernel(const float* __restrict__ emb) {
    int row  = blockIdx.x * 8 + threadIdx.y;
    int lane = threadIdx.x;
    float4 v = ((const float4*)(emb + (size_t)row * DDIM))[lane];
    float ss = v.x * v.x + v.y * v.y + v.z * v.z + v.w * v.w;
    #pragma unroll
    for (int o = 16; o; o >>= 1) ss += __shfl_xor_sync(0xFFFFFFFFu, ss, o);
    float inv = rsqrtf(fmaxf(ss, 1e-24f));
    inv = inv * (1.5f - 0.5f * ss * inv * inv);
    const float SC = 14.426950408889634f;   // 10 / ln(2)
    float z[4] = {v.x * inv, v.y * inv, v.z * inv, v.w * inv};
    __half a[4], b[4];
    #pragma unroll
    for (int k = 0; k < 4; k++) {
        a[k] = __float2half_rn(z[k] * SC);
        b[k] = __float2half_rn(z[k]);
    }
    size_t off = (size_t)row * DDIM + lane * 4;
    *(uint2*)(g_za + off) = *(uint2*)a;
    *(uint2*)(g_zb + off) = *(uint2*)b;
}

// ---- Kernel 2: upper-triangle tiles; pipelined fp16 GEMM + epilogue ----
__global__ void __launch_bounds__(256, 2)
main_kernel(const int* __restrict__ st, const int* __restrict__ cen) {
    extern __shared__ char smem[];
    const uint32_t sb = smem_u32(smem);
    const int tid   = threadIdx.x;
    const int wid   = tid >> 5;
    const int lane  = tid & 31;
    const int warpM = wid >> 1;
    const int warpN = wid & 1;

    // triangular decode
    const int t = blockIdx.x;
    int bx = (int)(64.5f - sqrtf(64.5f * 64.5f - 2.0f * (float)t));
    bx = bx < 0 ? 0 : (bx > 63 ? 63 : bx);
    #define FTRI(r) ((r) * NT - ((r) * ((r) - 1)) / 2)
    while (bx > 0 && FTRI(bx) > t) bx--;
    while (FTRI(bx + 1) <= t) bx++;
    const int by = bx + (t - FTRI(bx));
    const int rBase = bx * TM;
    const int cBase = by * TN;
    const bool isDiag = (bx == by);

    // Stage chunk c into buffer c as its own commit group.
    auto load_chunk = [&](int c) {
        uint32_t bA = sb + c * SM_STAGE;
        uint32_t bB = bA + 16384;
        #pragma unroll
        for (int u = 0; u < 4; u++) {
            int idx = u * 256 + tid;
            int row = idx >> 3, cc = idx & 7;
            uint32_t sw = (uint32_t)row * 128 + (uint32_t)((cc ^ (row & 7)) << 4);
            cp16(bA + sw, g_za + (size_t)(rBase + row) * DDIM + c * KC + cc * 8);
            cp16(bB + sw, g_zb + (size_t)(cBase + row) * DDIM + c * KC + cc * 8);
        }
        cp_commit();
    };
    load_chunk(0);
    load_chunk(1);

    int* sTi   = (int*)(smem + SM_TI);
    int* sCenR = (int*)(smem + SM_CENR);
    int* sTj   = (int*)(smem + SM_TJ);
    int* sCenC = (int*)(smem + SM_CENC);
    if (tid < 128) {
        sTi[tid]   = st[rBase + tid];
        sCenR[tid] = cen[rBase + tid];
    } else {
        sTj[tid - 128]   = st[cBase + tid - 128];
        sCenC[tid - 128] = cen[cBase + tid - 128];
    }

    // fp16 accumulators: acc[mf][nf][rg] packs cols (c2, c2+1) of row-group rg
    uint32_t acc[2][8][2];
    #pragma unroll
    for (int mf = 0; mf < 2; mf++)
        #pragma unroll
        for (int nf = 0; nf < 8; nf++) {
            acc[mf][nf][0] = 0u;
            acc[mf][nf][1] = 0u;
        }

    const int trow = lane & 7;
    const int tg1  = (lane >> 3) & 1;
    const int cadd = lane >> 4;
    const int rowA0 = warpM * 32 + tg1 * 8 + trow;
    const int rowB0 = warpN * 64 + tg1 * 8 + trow;

    // Pipelined: compute chunk 0 while chunk 1 is still in flight.
    #pragma unroll
    for (int c = 0; c < 2; c++) {
        if (c == 0) cp_wait<1>(); else cp_wait<0>();
        __syncthreads();
        uint32_t bA = sb + c * SM_STAGE;
        uint32_t bB = bA + 16384;
        #pragma unroll
        for (int kk = 0; kk < 4; kk++) {
            uint32_t aF[2][4], bF[4][4];
            #pragma unroll
            for (int mf = 0; mf < 2; mf++) {
                int row = rowA0 + mf * 16;
                uint32_t a = bA + row * 128 + (((kk * 2 + cadd) ^ (row & 7)) << 4);
                ldsm4(aF[mf][0], aF[mf][1], aF[mf][2], aF[mf][3], a);
            }
            #pragma unroll
            for (int np = 0; np < 4; np++) {
                int row = rowB0 + np * 16;
                uint32_t a = bB + row * 128 + (((kk * 2 + cadd) ^ (row & 7)) << 4);
                ldsm4(bF[np][0], bF[np][1], bF[np][2], bF[np][3], a);
            }
            #pragma unroll
            for (int mf = 0; mf < 2; mf++)
                #pragma unroll
                for (int np = 0; np < 4; np++) {
                    mma16816h(acc[mf][np * 2][0], acc[mf][np * 2][1],
                              aF[mf][0], aF[mf][1], aF[mf][2], aF[mf][3],
                              bF[np][0], bF[np][2]);
                    mma16816h(acc[mf][np * 2 + 1][0], acc[mf][np * 2 + 1][1],
                              aF[mf][0], aF[mf][1], aF[mf][2], aF[mf][3],
                              bF[np][1], bF[np][3]);
                }
        }
    }

    // -------- epilogue: acc = fp16 log2-domain logits; e = 2^acc --------
    const int q  = lane >> 2;
    const int c2 = (lane & 3) * 2;

    int lrw[4], rti[4], rcn[4];
    unsigned long long prs[4];   // packed (sum_all, sum_inwindow) per row slot
    #pragma unroll
    for (int u = 0; u < 4; u++) {
        lrw[u] = warpM * 32 + (u >> 1) * 16 + (u & 1) * 8 + q;
        rti[u] = sTi[lrw[u]];
        rcn[u] = sCenR[lrw[u]];
        prs[u] = 0ull;
    }

    float2* colp = (float2*)(smem + SM_COLP);   // [4 warpM][128 cols]

    if (!isDiag) {
        #pragma unroll
        for (int nf = 0; nf < 8; nf++) {
            const int lc0 = warpN * 64 + nf * 8 + c2;
            const int lc1 = lc0 + 1;
            const int tj0 = sTj[lc0], tj1 = sTj[lc1];
            unsigned long long pca0 = 0ull, pca1 = 0ull;
            #pragma unroll
            for (int u = 0; u < 4; u++) {
                const int mf = u >> 1;
                const int rg = u & 1;
                uint32_t eh = ex2h2(acc[mf][nf][rg]);
                float2 f = __half22float2(*reinterpret_cast<__half2*>(&eh));
                bool in0 = (unsigned)(rti[u] - tj0 + 364) <= 728u;
                bool in1 = (unsigned)(rti[u] - tj1 + 364) <= 728u;
                unsigned long long pk0 = pk2(f.x, in0 ? f.x : 0.0f);
                unsigned long long pk1 = pk2(f.y, in1 ? f.y : 0.0f);
                prs[u] = add2(prs[u], pk0);
                prs[u] = add2(prs[u], pk1);
                pca0 = add2(pca0, pk0);
                pca1 = add2(pca1, pk1);
            }
            float ca0, cw0, ca1, cw1;
            unpk2(pca0, ca0, cw0);
            unpk2(pca1, ca1, cw1);
            #pragma unroll
            for (int o = 4; o <= 16; o <<= 1) {
                ca0 += __shfl_xor_sync(0xFFFFFFFFu, ca0, o);
                cw0 += __shfl_xor_sync(0xFFFFFFFFu, cw0, o);
                ca1 += __shfl_xor_sync(0xFFFFFFFFu, ca1, o);
                cw1 += __shfl_xor_sync(0xFFFFFFFFu, cw1, o);
            }
            if (q == 0) {
                colp[warpM * 128 + lc0] =
                    make_float2(ca0, sCenC[lc0] ? cw0 : 0.0f);
                colp[warpM * 128 + lc1] =
                    make_float2(ca1, sCenC[lc1] ? cw1 : 0.0f);
            }
        }
    } else {
        #pragma unroll
        for (int nf = 0; nf < 8; nf++) {
            const int lc0 = warpN * 64 + nf * 8 + c2;
            const int lc1 = lc0 + 1;
            const int tj0 = sTj[lc0], tj1 = sTj[lc1];
            #pragma unroll
            for (int u = 0; u < 4; u++) {
                const int mf = u >> 1;
                const int rg = u & 1;
                uint32_t eh = ex2h2(acc[mf][nf][rg]);
                float2 f = __half22float2(*reinterpret_cast<__half2*>(&eh));
                bool in0 = (unsigned)(rti[u] - tj0 + 364) <= 728u;
                bool in1 = (unsigned)(rti[u] - tj1 + 364) <= 728u;
                if (lc0 != lrw[u]) prs[u] = add2(prs[u], pk2(f.x, in0 ? f.x : 0.0f));
                if (lc1 != lrw[u]) prs[u] = add2(prs[u], pk2(f.y, in1 ? f.y : 0.0f));
            }
        }
    }

    // ---- row-anchored writes (censor applied post-loop) ----
    #pragma unroll
    for (int u = 0; u < 4; u++) {
        float sa, sw;
        unpk2(prs[u], sa, sw);
        float sp = rcn[u] ? sw : 0.0f;
        #pragma unroll
        for (int o = 1; o <= 2; o <<= 1) {
            sa += __shfl_xor_sync(0xFFFFFFFFu, sa, o);
            sp += __shfl_xor_sync(0xFFFFFFFFu, sp, o);
        }
        if ((lane & 3) == 0)
            g_part[(size_t)(rBase + lrw[u]) * NSEG + 2 * by + warpN] =
                make_float2(sa, sp);
    }

    // ---- col-anchored writes (off-diagonal only) ----
    if (!isDiag) {
        __syncthreads();
        const int mhalf = tid >> 7;
        const int col   = tid & 127;
        float2 v0 = colp[(2 * mhalf) * 128 + col];
        float2 v1 = colp[(2 * mhalf + 1) * 128 + col];
        g_part[(size_t)(cBase + col) * NSEG + 2 * bx + mhalf] =
            make_float2(v0.x + v1.x, v0.y + v1.y);
    }
}

// ---- Kernel 3: per-row merge + block reduce + last-block final reduce ----
__global__ void combine_kernel(float* __restrict__ out) {
    __shared__ float sh_s[256], sh_c[256];
    __shared__ int s_last;
    int tid = threadIdx.x;
    int row = blockIdx.x * 256 + tid;
    float sa = 0.0f, sp = 0.0f;
    const float4* p = (const float4*)(g_part + (size_t)row * NSEG);
    #pragma unroll
    for (int s = 0; s < NSEG / 2; s++) {
        float4 v = p[s];
        sa += v.x + v.z;
        sp += v.y + v.w;
    }
    float pr = 0.0f, c = 0.0f;
    if (sp > 0.0f) { pr = __logf(sa) - __logf(sp); c = 1.0f; }
    sh_s[tid] = pr; sh_c[tid] = c;
    __syncthreads();
    #pragma unroll
    for (int o = 128; o > 0; o >>= 1) {
        if (tid < o) { sh_s[tid] += sh_s[tid + o]; sh_c[tid] += sh_c[tid + o]; }
        __syncthreads();
    }
    if (tid == 0) {
        g_bsum[blockIdx.x] = sh_s[0];
        g_bcnt[blockIdx.x] = sh_c[0];
        __threadfence();
        int tk = atomicAdd(&g_ticket, 1);
        s_last = (tk == (int)gridDim.x - 1);
    }
    __syncthreads();
    if (s_last && tid < 32) {
        float s = g_bsum[tid], cc = g_bcnt[tid];   // gridDim.x == 32
        #pragma unroll
        for (int o = 16; o; o >>= 1) {
            s  += __shfl_xor_sync(0xFFFFFFFFu, s, o);
            cc += __shfl_xor_sync(0xFFFFFFFFu, cc, o);
        }
        if (tid == 0) {
            out[0] = (cc > 0.0f) ? (s / cc) : 0.0f;
            g_ticket = 0;   // reset for graph replay
        }
    }
}

extern "C" void kernel_launch(void* const* d_in, const int* in_sizes, int n_in,
                              void* d_out, int out_size) {
    const float* emb = (const float*)d_in[0];
    const int*   st  = (const int*)d_in[1];
    const int*   cn  = (const int*)d_in[2];
    float* out = (float*)d_out;

    cudaFuncSetAttribute(main_kernel, cudaFuncAttributeMaxDynamicSharedMemorySize,
                         SMEM_TOTAL);

    norm_kernel<<<BDIM / 8, dim3(32, 8)>>>(emb);
    main_kernel<<<(NT * (NT + 1)) / 2, 256, SMEM_TOTAL>>>(st, cn);
    combine_kernel<<<BDIM / 256, 256>>>(out);
}

// round 11
// speedup vs baseline: 9.4813x; 1.0028x over previous
#include <cuda_runtime.h>
#include <cuda_fp16.h>
#include <cstdint>

// B=8192, D=128. sim = (Z Z^T)/0.1 with masked logsumexps -> scalar mean.
// fp16 GEMM (fp16 accum) on mma.sync, K=128, exp2-folded:
//   A = fp16(10*log2e * z), B = fp16(z); epilogue e = ex2.f16x2(acc).
// Upper-triangle 128x128 tiles, processed TWO per CTA (128x256 super-tile,
// shared A stage); warpN selects the sub-tile. Dual-anchor partial sums.
#define BDIM 8192
#define DDIM 128
#define TM   128
#define KC   64
#define NSEG 128
#define NT   64
#define TTHRESH 365
#define NCTA 1056            // sum over bx of ceil((64-bx)/2)

__device__ __half g_za[BDIM * DDIM];          // 2MB: fp16(14.427*z)
__device__ __half g_zb[BDIM * DDIM];          // 2MB: fp16(z)
__device__ float2 g_part[BDIM * NSEG];        // 8MB (zero-init; gap slots stay 0)
__device__ float  g_bsum[BDIM / 256];
__device__ float  g_bcnt[BDIM / 256];
__device__ int    g_ticket = 0;

// ---------------- PTX helpers ----------------
__device__ __forceinline__ uint32_t smem_u32(const void* p) {
    uint32_t a;
    asm("{ .reg .u64 t; cvta.to.shared.u64 t, %1; cvt.u32.u64 %0, t; }" : "=r"(a) : "l"(p));
    return a;
}
__device__ __forceinline__ void cp16(uint32_t dst, const void* src) {
    asm volatile("cp.async.cg.shared.global [%0], [%1], 16;" :: "r"(dst), "l"(src));
}
__device__ __forceinline__ void cp_commit() {
    asm volatile("cp.async.commit_group;" ::: "memory");
}
template <int N> __device__ __forceinline__ void cp_wait() {
    asm volatile("cp.async.wait_group %0;" :: "n"(N) : "memory");
}
__device__ __forceinline__ void ldsm4(uint32_t& r0, uint32_t& r1, uint32_t& r2,
                                      uint32_t& r3, uint32_t addr) {
    asm volatile("ldmatrix.sync.aligned.m8n8.x4.shared.b16 {%0,%1,%2,%3}, [%4];"
                 : "=r"(r0), "=r"(r1), "=r"(r2), "=r"(r3) : "r"(addr));
}
__device__ __forceinline__ void mma16816h(uint32_t& d0, uint32_t& d1,
                                          uint32_t a0, uint32_t a1, uint32_t a2,
                                          uint32_t a3, uint32_t b0, uint32_t b1) {
    asm volatile(
        "mma.sync.aligned.m16n8k16.row.col.f16.f16.f16.f16 "
        "{%0,%1}, {%2,%3,%4,%5}, {%6,%7}, {%0,%1};"
        : "+r"(d0), "+r"(d1)
        : "r"(a0), "r"(a1), "r"(a2), "r"(a3), "r"(b0), "r"(b1));
}
__device__ __forceinline__ uint32_t ex2h2(uint32_t x) {
    uint32_t r;
    asm("ex2.approx.f16x2 %0, %1;" : "=r"(r) : "r"(x));
    return r;
}
__device__ __forceinline__ unsigned long long pk2(float lo, float hi) {
    unsigned long long r;
    asm("mov.b64 %0, {%1, %2};" : "=l"(r) : "f"(lo), "f"(hi));
    return r;
}
__device__ __forceinline__ void unpk2(unsigned long long v, float& lo, float& hi) {
    asm("mov.b64 {%0, %1}, %2;" : "=f"(lo), "=f"(hi) : "l"(v));
}
__device__ __forceinline__ unsigned long long add2(unsigned long long a,
                                                   unsigned long long b) {
    unsigned long long d;
    asm("add.rn.f32x2 %0, %1, %2;" : "=l"(d) : "l"(a), "l"(b));
    return d;
}

// SMEM: 2 chunks x (A 16K + B 32K) | colp 8K | ti 512 | cenR 512 | tj 1K | cenC 1K
#define SM_STAGE 49152
#define SM_COLP  98304
#define SM_TI    106496
#define SM_CENR  107008
#define SM_TJ    107520
#define SM_CENC  108544
#define SMEM_TOTAL 109568

// pairs(r) = 32 - r/2 ; FT(r) = sum_{x<r} pairs(x) = 32r - s(r)
__device__ __forceinline__ int FT(int r) {
    int m = r >> 1;
    return 32 * r - (m * m - ((r & 1) ? 0 : m));
}

// ---- Kernel 1: normalize + fp16 encode (exp2 scale folded into A) ----
__global__ void norm_kernel(const float* __restrict__ emb) {
    int row  = blockIdx.x * 8 + threadIdx.y;
    int lane = threadIdx.x;
    float4 v = ((const float4*)(emb + (size_t)row * DDIM))[lane];
    float ss = v.x * v.x + v.y * v.y + v.z * v.z + v.w * v.w;
    #pragma unroll
    for (int o = 16; o; o >>= 1) ss += __shfl_xor_sync(0xFFFFFFFFu, ss, o);
    float inv = rsqrtf(fmaxf(ss, 1e-24f));
    inv = inv * (1.5f - 0.5f * ss * inv * inv);
    const float SC = 14.426950408889634f;   // 10 / ln(2)
    float z[4] = {v.x * inv, v.y * inv, v.z * inv, v.w * inv};
    __half a[4], b[4];
    #pragma unroll
    for (int k = 0; k < 4; k++) {
        a[k] = __float2half_rn(z[k] * SC);
        b[k] = __float2half_rn(z[k]);
    }
    size_t off = (size_t)row * DDIM + lane * 4;
    *(uint2*)(g_za + off) = *(uint2*)a;
    *(uint2*)(g_zb + off) = *(uint2*)b;
}

// ---- Kernel 2: 128x256 super-tiles on the upper triangle ----
__global__ void __launch_bounds__(256, 2)
main_kernel(const int* __restrict__ st, const int* __restrict__ cen) {
    extern __shared__ char smem[];
    const uint32_t sb = smem_u32(smem);
    const int tid   = threadIdx.x;
    const int wid   = tid >> 5;
    const int lane  = tid & 31;
    const int warpM = wid >> 1;
    const int warpN = wid & 1;          // sub-tile selector

    // decode blockIdx -> (bx, pair p); by0 = bx + 2p
    const int t = blockIdx.x;
    float disc = 4096.0f - 4.0f * (float)t;
    int bx = 64 - (int)sqrtf(fmaxf(disc, 0.0f));
    bx = bx < 0 ? 0 : (bx > 63 ? 63 : bx);
    while (bx > 0 && FT(bx) > t) bx--;
    while (bx < 63 && FT(bx + 1) <= t) bx++;
    const int p   = t - FT(bx);
    const int by0 = bx + 2 * p;
    const int rBase  = bx * TM;
    const int cBase0 = by0 * 128;
    const int by_s   = by0 + warpN;          // this warp's sub-tile
    const bool active = (by_s < NT);
    const bool isDiag = (by_s == bx);

    // Stage chunk c (A 128 rows, B 256 rows) as its own commit group.
    auto load_chunk = [&](int c) {
        uint32_t bA = sb + c * SM_STAGE;
        uint32_t bB = bA + 16384;
        #pragma unroll
        for (int u = 0; u < 4; u++) {
            int idx = u * 256 + tid;
            int row = idx >> 3, cc = idx & 7;
            uint32_t sw = (uint32_t)row * 128 + (uint32_t)((cc ^ (row & 7)) << 4);
            cp16(bA + sw, g_za + (size_t)(rBase + row) * DDIM + c * KC + cc * 8);
        }
        #pragma unroll
        for (int u = 0; u < 8; u++) {
            int idx = u * 256 + tid;
            int row = idx >> 3, cc = idx & 7;
            int gr = cBase0 + row;
            gr = gr > 8191 ? 8191 : gr;   // clamp for inactive second sub-tile
            uint32_t sw = (uint32_t)row * 128 + (uint32_t)((cc ^ (row & 7)) << 4);
            cp16(bB + sw, g_zb + (size_t)gr * DDIM + c * KC + cc * 8);
        }
        cp_commit();
    };
    load_chunk(0);
    load_chunk(1);

    int* sTi   = (int*)(smem + SM_TI);
    int* sCenR = (int*)(smem + SM_CENR);
    int* sTj   = (int*)(smem + SM_TJ);
    int* sCenC = (int*)(smem + SM_CENC);
    {
        int gc = cBase0 + tid;
        gc = gc > 8191 ? 8191 : gc;
        sTj[tid]   = st[gc];
        sCenC[tid] = cen[gc];
        if (tid < 128) {
            sTi[tid]   = st[rBase + tid];
            sCenR[tid] = cen[rBase + tid];
        }
    }

    // fp16 accumulators: acc[mf][nf][rg], nf 0..15 covers this CTA's 256 cols
    uint32_t acc[2][16][2];
    #pragma unroll
    for (int mf = 0; mf < 2; mf++)
        #pragma unroll
        for (int nf = 0; nf < 16; nf++) {
            acc[mf][nf][0] = 0u;
            acc[mf][nf][1] = 0u;
        }

    const int trow = lane & 7;
    const int tg1  = (lane >> 3) & 1;
    const int cadd = lane >> 4;
    const int rowA0 = warpM * 32 + tg1 * 8 + trow;
    const int rowB0 = warpN * 128 + tg1 * 8 + trow;

    #pragma unroll
    for (int c = 0; c < 2; c++) {
        if (c == 0) cp_wait<1>(); else cp_wait<0>();
        __syncthreads();
        uint32_t bA = sb + c * SM_STAGE;
        uint32_t bB = bA + 16384;
        #pragma unroll
        for (int kk = 0; kk < 4; kk++) {
            uint32_t aF[2][4];
            #pragma unroll
            for (int mf = 0; mf < 2; mf++) {
                int row = rowA0 + mf * 16;
                uint32_t a = bA + row * 128 + (((kk * 2 + cadd) ^ (row & 7)) << 4);
                ldsm4(aF[mf][0], aF[mf][1], aF[mf][2], aF[mf][3], a);
            }
            #pragma unroll
            for (int h = 0; h < 2; h++) {         // np halves: keeps bF at 16 regs
                uint32_t bF[4][4];
                #pragma unroll
                for (int n4 = 0; n4 < 4; n4++) {
                    int row = rowB0 + (h * 4 + n4) * 16;
                    uint32_t a = bB + row * 128 + (((kk * 2 + cadd) ^ (row & 7)) << 4);
                    ldsm4(bF[n4][0], bF[n4][1], bF[n4][2], bF[n4][3], a);
                }
                #pragma unroll
                for (int mf = 0; mf < 2; mf++)
                    #pragma unroll
                    for (int n4 = 0; n4 < 4; n4++) {
                        int nf = (h * 4 + n4) * 2;
                        mma16816h(acc[mf][nf][0], acc[mf][nf][1],
                                  aF[mf][0], aF[mf][1], aF[mf][2], aF[mf][3],
                                  bF[n4][0], bF[n4][2]);
                        mma16816h(acc[mf][nf + 1][0], acc[mf][nf + 1][1],
                                  aF[mf][0], aF[mf][1], aF[mf][2], aF[mf][3],
                                  bF[n4][1], bF[n4][3]);
                    }
            }
        }
    }

    // -------- epilogue: acc = fp16 log2-domain logits; e = 2^acc --------
    const int q  = lane >> 2;
    const int c2 = (lane & 3) * 2;

    int lrw[4], rti[4], rcn[4];
    unsigned long long prs[4];
    #pragma unroll
    for (int u = 0; u < 4; u++) {
        lrw[u] = warpM * 32 + (u >> 1) * 16 + (u & 1) * 8 + q;
        rti[u] = sTi[lrw[u]];
        rcn[u] = sCenR[lrw[u]];
        prs[u] = 0ull;
    }

    float2* colp = (float2*)(smem + SM_COLP);   // [2 warpN][4 warpM][128]

    if (active && !isDiag) {
        #pragma unroll
        for (int nf = 0; nf < 16; nf++) {
            const int lc0 = nf * 8 + c2;
            const int lc1 = lc0 + 1;
            const int tj0 = sTj[warpN * 128 + lc0];
            const int tj1 = sTj[warpN * 128 + lc1];
            unsigned long long pca0 = 0ull, pca1 = 0ull;
            #pragma unroll
            for (int u = 0; u < 4; u++) {
                const int mf = u >> 1;
                const int rg = u & 1;
                uint32_t eh = ex2h2(acc[mf][nf][rg]);
                float2 f = __half22float2(*reinterpret_cast<__half2*>(&eh));
                bool in0 = (unsigned)(rti[u] - tj0 + 364) <= 728u;
                bool in1 = (unsigned)(rti[u] - tj1 + 364) <= 728u;
                unsigned long long pk0 = pk2(f.x, in0 ? f.x : 0.0f);
                unsigned long long pk1 = pk2(f.y, in1 ? f.y : 0.0f);
                prs[u] = add2(prs[u], pk0);
                prs[u] = add2(prs[u], pk1);
                pca0 = add2(pca0, pk0);
                pca1 = add2(pca1, pk1);
            }
            float ca0, cw0, ca1, cw1;
            unpk2(pca0, ca0, cw0);
            unpk2(pca1, ca1, cw1);
            #pragma unroll
            for (int o = 4; o <= 16; o <<= 1) {
                ca0 += __shfl_xor_sync(0xFFFFFFFFu, ca0, o);
                cw0 += __shfl_xor_sync(0xFFFFFFFFu, cw0, o);
                ca1 += __shfl_xor_sync(0xFFFFFFFFu, ca1, o);
                cw1 += __shfl_xor_sync(0xFFFFFFFFu, cw1, o);
            }
            if (q == 0) {
                colp[(warpN * 4 + warpM) * 128 + lc0] =
                    make_float2(ca0, sCenC[warpN * 128 + lc0] ? cw0 : 0.0f);
                colp[(warpN * 4 + warpM) * 128 + lc1] =
                    make_float2(ca1, sCenC[warpN * 128 + lc1] ? cw1 : 0.0f);
            }
        }
    } else if (active) {   // diagonal sub-tile: self exclusion, row sums only
        #pragma unroll
        for (int nf = 0; nf < 16; nf++) {
            const int lc0 = nf * 8 + c2;
            const int lc1 = lc0 + 1;
            const int tj0 = sTj[warpN * 128 + lc0];
            const int tj1 = sTj[warpN * 128 + lc1];
            #pragma unroll
            for (int u = 0; u < 4; u++) {
                const int mf = u >> 1;
                const int rg = u & 1;
                uint32_t eh = ex2h2(acc[mf][nf][rg]);
                float2 f = __half22float2(*reinterpret_cast<__half2*>(&eh));
                bool in0 = (unsigned)(rti[u] - tj0 + 364) <= 728u;
                bool in1 = (unsigned)(rti[u] - tj1 + 364) <= 728u;
                if (lc0 != lrw[u]) prs[u] = add2(prs[u], pk2(f.x, in0 ? f.x : 0.0f));
                if (lc1 != lrw[u]) prs[u] = add2(prs[u], pk2(f.y, in1 ? f.y : 0.0f));
            }
        }
    }

    // ---- row-anchored writes: slot 64 + by_s ----
    if (active) {
        #pragma unroll
        for (int u = 0; u < 4; u++) {
            float sa, sw;
            unpk2(prs[u], sa, sw);
            float sp = rcn[u] ? sw : 0.0f;
            #pragma unroll
            for (int o = 1; o <= 2; o <<= 1) {
                sa += __shfl_xor_sync(0xFFFFFFFFu, sa, o);
                sp += __shfl_xor_sync(0xFFFFFFFFu, sp, o);
            }
            if ((lane & 3) == 0)
                g_part[(size_t)(rBase + lrw[u]) * NSEG + 64 + by_s] =
                    make_float2(sa, sp);
        }
    }

    // ---- col-anchored writes: slot 2*bx + mhalf ----
    __syncthreads();
    #pragma unroll
    for (int it = 0; it < 2; it++) {
        int idx = it * 256 + tid;            // 0..511
        int s   = idx >> 8;
        int mh  = (idx >> 7) & 1;
        int col = idx & 127;
        int bys = by0 + s;
        if (bys < NT && bys != bx) {
            float2 v0 = colp[(s * 4 + 2 * mh) * 128 + col];
            float2 v1 = colp[(s * 4 + 2 * mh + 1) * 128 + col];
            g_part[(size_t)(bys * 128 + col) * NSEG + 2 * bx + mh] =
                make_float2(v0.x + v1.x, v0.y + v1.y);
        }
    }
}

// ---- Kernel 3: per-row merge + block reduce + last-block final reduce ----
__global__ void combine_kernel(float* __restrict__ out) {
    __shared__ float sh_s[256], sh_c[256];
    __shared__ int s_last;
    int tid = threadIdx.x;
    int row = blockIdx.x * 256 + tid;
    float sa = 0.0f, sp = 0.0f;
    const float4* p = (const float4*)(g_part + (size_t)row * NSEG);
    #pragma unroll
    for (int s = 0; s < NSEG / 2; s++) {
        float4 v = p[s];
        sa += v.x + v.z;
        sp += v.y + v.w;
    }
    float pr = 0.0f, c = 0.0f;
    if (sp > 0.0f) { pr = __logf(sa) - __logf(sp); c = 1.0f; }
    sh_s[tid] = pr; sh_c[tid] = c;
    __syncthreads();
    #pragma unroll
    for (int o = 128; o > 0; o >>= 1) {
        if (tid < o) { sh_s[tid] += sh_s[tid + o]; sh_c[tid] += sh_c[tid + o]; }
        __syncthreads();
    }
    if (tid == 0) {
        g_bsum[blockIdx.x] = sh_s[0];
        g_bcnt[blockIdx.x] = sh_c[0];
        __threadfence();
        int tk = atomicAdd(&g_ticket, 1);
        s_last = (tk == (int)gridDim.x - 1);
    }
    __syncthreads();
    if (s_last && tid < 32) {
        float s = g_bsum[tid], cc = g_bcnt[tid];   // gridDim.x == 32
        #pragma unroll
        for (int o = 16; o; o >>= 1) {
            s  += __shfl_xor_sync(0xFFFFFFFFu, s, o);
            cc += __shfl_xor_sync(0xFFFFFFFFu, cc, o);
        }
        if (tid == 0) {
            out[0] = (cc > 0.0f) ? (s / cc) : 0.0f;
            g_ticket = 0;   // reset for graph replay
        }
    }
}

extern "C" void kernel_launch(void* const* d_in, const int* in_sizes, int n_in,
                              void* d_out, int out_size) {
    const float* emb = (const float*)d_in[0];
    const int*   st  = (const int*)d_in[1];
    const int*   cn  = (const int*)d_in[2];
    float* out = (float*)d_out;

    cudaFuncSetAttribute(main_kernel, cudaFuncAttributeMaxDynamicSharedMemorySize,
                         SMEM_TOTAL);

    norm_kernel<<<BDIM / 8, dim3(32, 8)>>>(emb);
    main_kernel<<<NCTA, 256, SMEM_TOTAL>>>(st, cn);
    combine_kernel<<<BDIM / 256, 256>>>(out);
}